// round 1
// baseline (speedup 1.0000x reference)
#include <cuda_runtime.h>
#include <math.h>

#define NN   10000
#define EE   640000
#define TOTE (EE + NN)
#define FULL 0xFFFFFFFFu

// ---------------- scratch (static device globals; no allocation) ----------------
__device__ int   g_deg[NN];
__device__ int   g_rowptr[NN + 1];
__device__ int   g_cursor[NN];
__device__ int   g_csr[TOTE];

__device__ float g_h1[NN * 128];   // x @ W1
__device__ float g_o1[NN * 128];   // elu(gat1)
__device__ float g_h2[NN * 128];   // o1 @ W2
__device__ float g_o2[NN * 128];   // elu(gat2)

__device__ float g_as1[NN * 4];
__device__ float g_ad1[NN * 4];
__device__ float g_as2[NN];
__device__ float g_ad2[NN];

__device__ __forceinline__ float lrelu(float v) { return v > 0.f ? v : 0.2f * v; }
__device__ __forceinline__ float elu(float v)   { return v > 0.f ? v : (expf(v) - 1.f); }

// ---------------- CSR build ----------------
__global__ void init_deg_k(int n) {
    int i = blockIdx.x * blockDim.x + threadIdx.x;
    if (i < n) g_deg[i] = 1;                    // self loop
}

__global__ void hist_k(const int* __restrict__ ei, int e) {
    int i = blockIdx.x * blockDim.x + threadIdx.x;
    if (i < e) atomicAdd(&g_deg[ei[e + i]], 1); // dst row of edge_index
}

__global__ void scan_k(int n) {
    __shared__ int wsum[32];
    __shared__ int carry;
    int t = threadIdx.x, lane = t & 31, wid = t >> 5;
    if (t == 0) carry = 0;
    __syncthreads();
    for (int base = 0; base < n; base += 1024) {
        int idx = base + t;
        int v = (idx < n) ? g_deg[idx] : 0;
        int incl = v;
        #pragma unroll
        for (int off = 1; off < 32; off <<= 1) {
            int y = __shfl_up_sync(FULL, incl, off);
            if (lane >= off) incl += y;
        }
        if (lane == 31) wsum[wid] = incl;
        __syncthreads();
        if (wid == 0) {
            int wv = wsum[lane];
            int wi = wv;
            #pragma unroll
            for (int off = 1; off < 32; off <<= 1) {
                int y = __shfl_up_sync(FULL, wi, off);
                if (lane >= off) wi += y;
            }
            wsum[lane] = wi - wv;               // exclusive warp offsets
        }
        __syncthreads();
        int excl = carry + wsum[wid] + incl - v;
        if (idx < n) { g_rowptr[idx] = excl; g_cursor[idx] = excl; }
        __syncthreads();
        if (t == 1023) carry = excl + v;        // = carry_old + chunk total
        __syncthreads();
    }
    if (t == 0) g_rowptr[n] = carry;
}

__global__ void fill_k(const int* __restrict__ ei, int e, int n) {
    int i = blockIdx.x * blockDim.x + threadIdx.x;
    if (i >= e + n) return;
    int s, d;
    if (i < e) { s = ei[i]; d = ei[e + i]; }
    else       { s = d = i - e; }
    int pos = atomicAdd(&g_cursor[d], 1);
    g_csr[pos] = s;
}

// ---------------- GEMM: C[n,128] = A[n,128] @ B[128,128] ----------------
__global__ void gemm128_k(const float* __restrict__ A, const float* __restrict__ B,
                          float* __restrict__ C, int n) {
    __shared__ __align__(16) float xs[32][128];
    int row0 = blockIdx.x * 32;
    int t = threadIdx.x;                        // 128 threads; t = output column
    for (int i = t; i < 32 * 128; i += 128) {
        int r = i >> 7, k = i & 127;
        xs[r][k] = (row0 + r < n) ? A[(row0 + r) * 128 + k] : 0.f;
    }
    __syncthreads();
    float acc[32];
    #pragma unroll
    for (int r = 0; r < 32; r++) acc[r] = 0.f;
    for (int k = 0; k < 128; k += 4) {
        float w0 = B[(k + 0) * 128 + t];
        float w1 = B[(k + 1) * 128 + t];
        float w2 = B[(k + 2) * 128 + t];
        float w3 = B[(k + 3) * 128 + t];
        #pragma unroll
        for (int r = 0; r < 32; r++) {
            float4 xv = *(const float4*)&xs[r][k];
            acc[r] += xv.x * w0 + xv.y * w1 + xv.z * w2 + xv.w * w3;
        }
    }
    for (int r = 0; r < 32; r++) {
        int row = row0 + r;
        if (row < n) C[row * 128 + t] = acc[r];
    }
}

// ---------------- per-node attention scalars ----------------
// layer1: 4 heads of 32 dims. one warp per node.
__global__ void avec1_k(const float* __restrict__ h, const float* __restrict__ a_src,
                        const float* __restrict__ a_dst, int n) {
    int w = (blockIdx.x * blockDim.x + threadIdx.x) >> 5;
    int lane = threadIdx.x & 31;
    if (w >= n) return;
    float4 hv = *(const float4*)&h[w * 128 + lane * 4];
    float4 sv = *(const float4*)&a_src[lane * 4];
    float4 dv = *(const float4*)&a_dst[lane * 4];
    float ps = hv.x * sv.x + hv.y * sv.y + hv.z * sv.z + hv.w * sv.w;
    float pd = hv.x * dv.x + hv.y * dv.y + hv.z * dv.z + hv.w * dv.w;
    #pragma unroll
    for (int off = 1; off < 8; off <<= 1) {
        ps += __shfl_xor_sync(FULL, ps, off);
        pd += __shfl_xor_sync(FULL, pd, off);
    }
    if ((lane & 7) == 0) {
        g_as1[w * 4 + (lane >> 3)] = ps;
        g_ad1[w * 4 + (lane >> 3)] = pd;
    }
}

// layer2: 1 head of 128 dims.
__global__ void avec2_k(const float* __restrict__ h, const float* __restrict__ a_src,
                        const float* __restrict__ a_dst, int n) {
    int w = (blockIdx.x * blockDim.x + threadIdx.x) >> 5;
    int lane = threadIdx.x & 31;
    if (w >= n) return;
    float4 hv = *(const float4*)&h[w * 128 + lane * 4];
    float4 sv = *(const float4*)&a_src[lane * 4];
    float4 dv = *(const float4*)&a_dst[lane * 4];
    float ps = hv.x * sv.x + hv.y * sv.y + hv.z * sv.z + hv.w * sv.w;
    float pd = hv.x * dv.x + hv.y * dv.y + hv.z * dv.z + hv.w * dv.w;
    #pragma unroll
    for (int off = 1; off < 32; off <<= 1) {
        ps += __shfl_xor_sync(FULL, ps, off);
        pd += __shfl_xor_sync(FULL, pd, off);
    }
    if (lane == 0) { g_as2[w] = ps; g_ad2[w] = pd; }
}

// ---------------- GAT aggregation, layer 1 (4 heads) ----------------
// one warp per dst node. lane owns dims [lane*4, lane*4+4); head = lane>>3.
__global__ void att1_k(const float* __restrict__ h, const float* __restrict__ b,
                       float* __restrict__ out, int n) {
    int node = (blockIdx.x * blockDim.x + threadIdx.x) >> 5;
    int lane = threadIdx.x & 31;
    if (node >= n) return;
    int s0 = g_rowptr[node], s1 = g_rowptr[node + 1];

    float4 adv = *(const float4*)&g_ad1[node * 4];
    float m0 = -INFINITY, m1 = -INFINITY, m2 = -INFINITY, m3 = -INFINITY;
    for (int j = s0 + lane; j < s1; j += 32) {
        int s = g_csr[j];
        float4 asv = *(const float4*)&g_as1[s * 4];
        m0 = fmaxf(m0, lrelu(asv.x + adv.x));
        m1 = fmaxf(m1, lrelu(asv.y + adv.y));
        m2 = fmaxf(m2, lrelu(asv.z + adv.z));
        m3 = fmaxf(m3, lrelu(asv.w + adv.w));
    }
    #pragma unroll
    for (int off = 16; off; off >>= 1) {
        m0 = fmaxf(m0, __shfl_xor_sync(FULL, m0, off));
        m1 = fmaxf(m1, __shfl_xor_sync(FULL, m1, off));
        m2 = fmaxf(m2, __shfl_xor_sync(FULL, m2, off));
        m3 = fmaxf(m3, __shfl_xor_sync(FULL, m3, off));
    }

    int head = lane >> 3;
    float4 acc = make_float4(0.f, 0.f, 0.f, 0.f);
    float z0 = 0.f, z1 = 0.f, z2 = 0.f, z3 = 0.f;

    for (int base = s0; base < s1; base += 32) {
        int j = base + lane;
        int s = 0;
        float p0 = 0.f, p1 = 0.f, p2 = 0.f, p3 = 0.f;
        if (j < s1) {
            s = g_csr[j];
            float4 asv = *(const float4*)&g_as1[s * 4];
            p0 = __expf(lrelu(asv.x + adv.x) - m0);
            p1 = __expf(lrelu(asv.y + adv.y) - m1);
            p2 = __expf(lrelu(asv.z + adv.z) - m2);
            p3 = __expf(lrelu(asv.w + adv.w) - m3);
            z0 += p0; z1 += p1; z2 += p2; z3 += p3;
        }
        int cnt = min(32, s1 - base);
        for (int jj = 0; jj < cnt; jj++) {
            int   ss = __shfl_sync(FULL, s,  jj);
            float q0 = __shfl_sync(FULL, p0, jj);
            float q1 = __shfl_sync(FULL, p1, jj);
            float q2 = __shfl_sync(FULL, p2, jj);
            float q3 = __shfl_sync(FULL, p3, jj);
            float q  = head == 0 ? q0 : head == 1 ? q1 : head == 2 ? q2 : q3;
            float4 hv = *(const float4*)&h[ss * 128 + lane * 4];
            acc.x += q * hv.x; acc.y += q * hv.y; acc.z += q * hv.z; acc.w += q * hv.w;
        }
    }
    #pragma unroll
    for (int off = 16; off; off >>= 1) {
        z0 += __shfl_xor_sync(FULL, z0, off);
        z1 += __shfl_xor_sync(FULL, z1, off);
        z2 += __shfl_xor_sync(FULL, z2, off);
        z3 += __shfl_xor_sync(FULL, z3, off);
    }
    float z = head == 0 ? z0 : head == 1 ? z1 : head == 2 ? z2 : z3;
    float inv = 1.f / z;
    int c = lane * 4;
    float4 bv = *(const float4*)&b[c];
    float4 o;
    o.x = elu(acc.x * inv + bv.x);
    o.y = elu(acc.y * inv + bv.y);
    o.z = elu(acc.z * inv + bv.z);
    o.w = elu(acc.w * inv + bv.w);
    *(float4*)&out[node * 128 + c] = o;
}

// ---------------- GAT aggregation, layer 2 (1 head) ----------------
__global__ void att2_k(const float* __restrict__ h, const float* __restrict__ b,
                       float* __restrict__ out, int n) {
    int node = (blockIdx.x * blockDim.x + threadIdx.x) >> 5;
    int lane = threadIdx.x & 31;
    if (node >= n) return;
    int s0 = g_rowptr[node], s1 = g_rowptr[node + 1];

    float ad = g_ad2[node];
    float m = -INFINITY;
    for (int j = s0 + lane; j < s1; j += 32)
        m = fmaxf(m, lrelu(g_as2[g_csr[j]] + ad));
    #pragma unroll
    for (int off = 16; off; off >>= 1)
        m = fmaxf(m, __shfl_xor_sync(FULL, m, off));

    float4 acc = make_float4(0.f, 0.f, 0.f, 0.f);
    float z = 0.f;
    for (int base = s0; base < s1; base += 32) {
        int j = base + lane;
        int s = 0; float p = 0.f;
        if (j < s1) {
            s = g_csr[j];
            p = __expf(lrelu(g_as2[s] + ad) - m);
            z += p;
        }
        int cnt = min(32, s1 - base);
        for (int jj = 0; jj < cnt; jj++) {
            int   ss = __shfl_sync(FULL, s, jj);
            float q  = __shfl_sync(FULL, p, jj);
            float4 hv = *(const float4*)&h[ss * 128 + lane * 4];
            acc.x += q * hv.x; acc.y += q * hv.y; acc.z += q * hv.z; acc.w += q * hv.w;
        }
    }
    #pragma unroll
    for (int off = 16; off; off >>= 1)
        z += __shfl_xor_sync(FULL, z, off);
    float inv = 1.f / z;
    int c = lane * 4;
    float4 bv = *(const float4*)&b[c];
    float4 o;
    o.x = elu(acc.x * inv + bv.x);
    o.y = elu(acc.y * inv + bv.y);
    o.z = elu(acc.z * inv + bv.z);
    o.w = elu(acc.w * inv + bv.w);
    *(float4*)&out[node * 128 + c] = o;
}

// ---------------- final linear head: [n,128] @ [128,40] + b ----------------
__global__ void head_k(const float* __restrict__ A, const float* __restrict__ W,
                       const float* __restrict__ b, float* __restrict__ out, int n) {
    int i = blockIdx.x * blockDim.x + threadIdx.x;
    if (i >= n * 40) return;
    int row = i / 40, c = i - row * 40;
    const float* xr = &A[row * 128];
    float acc = b[c];
    #pragma unroll 8
    for (int k = 0; k < 128; k++)
        acc += xr[k] * W[k * 40 + c];
    out[i] = acc;
}

// ---------------- launch ----------------
extern "C" void kernel_launch(void* const* d_in, const int* in_sizes, int n_in,
                              void* d_out, int out_size) {
    const float* x   = (const float*)d_in[0];
    const int*   ei  = (const int*)  d_in[1];
    const float* W1  = (const float*)d_in[2];
    const float* as1 = (const float*)d_in[3];
    const float* ad1 = (const float*)d_in[4];
    const float* b1  = (const float*)d_in[5];
    const float* W2  = (const float*)d_in[6];
    const float* as2 = (const float*)d_in[7];
    const float* ad2 = (const float*)d_in[8];
    const float* b2  = (const float*)d_in[9];
    const float* Wl  = (const float*)d_in[10];
    const float* bl  = (const float*)d_in[11];
    float* out = (float*)d_out;

    const int n = in_sizes[0] / 128;   // 10000
    const int e = in_sizes[1] / 2;     // 640000

    float *h1, *o1, *h2, *o2;
    cudaGetSymbolAddress((void**)&h1, g_h1);
    cudaGetSymbolAddress((void**)&o1, g_o1);
    cudaGetSymbolAddress((void**)&h2, g_h2);
    cudaGetSymbolAddress((void**)&o2, g_o2);

    // CSR build
    init_deg_k<<<(n + 255) / 256, 256>>>(n);
    hist_k<<<(e + 255) / 256, 256>>>(ei, e);
    scan_k<<<1, 1024>>>(n);
    fill_k<<<(e + n + 255) / 256, 256>>>(ei, e, n);

    // layer 1
    gemm128_k<<<(n + 31) / 32, 128>>>(x, W1, h1, n);
    avec1_k<<<(n * 32 + 255) / 256, 256>>>(h1, as1, ad1, n);
    att1_k<<<(n * 32 + 255) / 256, 256>>>(h1, b1, o1, n);

    // layer 2
    gemm128_k<<<(n + 31) / 32, 128>>>(o1, W2, h2, n);
    avec2_k<<<(n * 32 + 255) / 256, 256>>>(h2, as2, ad2, n);
    att2_k<<<(n * 32 + 255) / 256, 256>>>(h2, b2, o2, n);

    // head
    head_k<<<(n * 40 + 255) / 256, 256>>>(o2, Wl, bl, out, n);
}

// round 3
// speedup vs baseline: 1.1819x; 1.1819x over previous
#include <cuda_runtime.h>
#include <math.h>

#define NN   10000
#define EE   640000
#define TOTE (EE + NN)
#define FULL 0xFFFFFFFFu

// ---------------- scratch (static device globals; no allocation) ----------------
__device__ int   g_deg[NN];
__device__ int   g_rowptr[NN + 1];
__device__ int   g_cursor[NN];
__device__ int   g_csr[TOTE];

__device__ float g_h1[NN * 128];   // x @ W1
__device__ float g_o1[NN * 128];   // elu(gat1)
__device__ float g_h2[NN * 128];   // o1 @ W2
__device__ float g_o2[NN * 128];   // elu(gat2)

__device__ float g_as1[NN * 4];
__device__ float g_ad1[NN * 4];
__device__ float g_as2[NN];
__device__ float g_ad2[NN];

__device__ __forceinline__ float lrelu(float v) { return v > 0.f ? v : 0.2f * v; }
__device__ __forceinline__ float elu(float v)   { return v > 0.f ? v : (expf(v) - 1.f); }

// ---------------- CSR build ----------------
__global__ void init_deg_k(int n) {
    int i = blockIdx.x * blockDim.x + threadIdx.x;
    if (i < n) g_deg[i] = 1;                    // self loop
}

// 4 edges per thread (vectorized) for MLP on the atomics
__global__ void hist_k(const int* __restrict__ ei, int e) {
    int i = blockIdx.x * blockDim.x + threadIdx.x;
    int q = e >> 2;
    if (i < q) {
        int4 d = ((const int4*)(ei + e))[i];
        atomicAdd(&g_deg[d.x], 1);
        atomicAdd(&g_deg[d.y], 1);
        atomicAdd(&g_deg[d.z], 1);
        atomicAdd(&g_deg[d.w], 1);
    } else {
        int r = (q << 2) + (i - q);             // scalar tail (e % 4 edges)
        if (r < e) atomicAdd(&g_deg[ei[e + r]], 1);
    }
}

// single-pass block scan: 1024 threads, each owns `items` contiguous elements
__global__ void scan_k(int n) {
    __shared__ int wsum[32];
    int t = threadIdx.x, lane = t & 31, wid = t >> 5;
    int items = (n + 1023) >> 10;               // 10 for n=10000
    int base = t * items;
    int v[16];
    int sum = 0;
    #pragma unroll
    for (int i = 0; i < 16; i++) {
        if (i >= items) break;
        int idx = base + i;
        int x = (idx < n) ? g_deg[idx] : 0;
        v[i] = sum;                             // thread-local exclusive prefix
        sum += x;
    }
    int incl = sum;
    #pragma unroll
    for (int off = 1; off < 32; off <<= 1) {
        int y = __shfl_up_sync(FULL, incl, off);
        if (lane >= off) incl += y;
    }
    if (lane == 31) wsum[wid] = incl;
    __syncthreads();
    if (wid == 0) {
        int wv = wsum[lane];
        int wi = wv;
        #pragma unroll
        for (int off = 1; off < 32; off <<= 1) {
            int y = __shfl_up_sync(FULL, wi, off);
            if (lane >= off) wi += y;
        }
        wsum[lane] = wi - wv;                   // exclusive warp offsets
    }
    __syncthreads();
    int off = wsum[wid] + incl - sum;           // exclusive offset for this thread
    #pragma unroll
    for (int i = 0; i < 16; i++) {
        if (i >= items) break;
        int idx = base + i;
        if (idx < n) { int p = off + v[i]; g_rowptr[idx] = p; g_cursor[idx] = p; }
    }
    if (t == 1023) g_rowptr[n] = off + sum;     // grand total
}

// 4 edges per thread + self-loop range folded in
__global__ void fill_k(const int* __restrict__ ei, int e, int n) {
    int i = blockIdx.x * blockDim.x + threadIdx.x;
    int q = e >> 2;
    if (i < q) {
        int4 s = ((const int4*)ei)[i];
        int4 d = ((const int4*)(ei + e))[i];
        g_csr[atomicAdd(&g_cursor[d.x], 1)] = s.x;
        g_csr[atomicAdd(&g_cursor[d.y], 1)] = s.y;
        g_csr[atomicAdd(&g_cursor[d.z], 1)] = s.z;
        g_csr[atomicAdd(&g_cursor[d.w], 1)] = s.w;
    } else {
        int r = i - q;
        int tail = e & 3;
        if (r < tail) {                         // scalar tail edges
            int idx = (q << 2) + r;
            g_csr[atomicAdd(&g_cursor[ei[e + idx]], 1)] = ei[idx];
        } else {
            int node = r - tail;                // self loops
            if (node < n) g_csr[atomicAdd(&g_cursor[node], 1)] = node;
        }
    }
}

// ---------------- GEMM: C[n,128] = A[n,128] @ B[128,128] ----------------
__global__ void gemm128_k(const float* __restrict__ A, const float* __restrict__ B,
                          float* __restrict__ C, int n) {
    __shared__ __align__(16) float xs[32][128];
    int row0 = blockIdx.x * 32;
    int t = threadIdx.x;                        // 128 threads; t = output column
    for (int i = t; i < 32 * 128; i += 128) {
        int r = i >> 7, k = i & 127;
        xs[r][k] = (row0 + r < n) ? A[(row0 + r) * 128 + k] : 0.f;
    }
    __syncthreads();
    float acc[32];
    #pragma unroll
    for (int r = 0; r < 32; r++) acc[r] = 0.f;
    for (int k = 0; k < 128; k += 4) {
        float w0 = B[(k + 0) * 128 + t];
        float w1 = B[(k + 1) * 128 + t];
        float w2 = B[(k + 2) * 128 + t];
        float w3 = B[(k + 3) * 128 + t];
        #pragma unroll
        for (int r = 0; r < 32; r++) {
            float4 xv = *(const float4*)&xs[r][k];
            acc[r] += xv.x * w0 + xv.y * w1 + xv.z * w2 + xv.w * w3;
        }
    }
    for (int r = 0; r < 32; r++) {
        int row = row0 + r;
        if (row < n) C[row * 128 + t] = acc[r];
    }
}

// ---------------- per-node attention scalars ----------------
__global__ void avec1_k(const float* __restrict__ h, const float* __restrict__ a_src,
                        const float* __restrict__ a_dst, int n) {
    int w = (blockIdx.x * blockDim.x + threadIdx.x) >> 5;
    int lane = threadIdx.x & 31;
    if (w >= n) return;
    float4 hv = *(const float4*)&h[w * 128 + lane * 4];
    float4 sv = *(const float4*)&a_src[lane * 4];
    float4 dv = *(const float4*)&a_dst[lane * 4];
    float ps = hv.x * sv.x + hv.y * sv.y + hv.z * sv.z + hv.w * sv.w;
    float pd = hv.x * dv.x + hv.y * dv.y + hv.z * dv.z + hv.w * dv.w;
    #pragma unroll
    for (int off = 1; off < 8; off <<= 1) {
        ps += __shfl_xor_sync(FULL, ps, off);
        pd += __shfl_xor_sync(FULL, pd, off);
    }
    if ((lane & 7) == 0) {
        g_as1[w * 4 + (lane >> 3)] = ps;
        g_ad1[w * 4 + (lane >> 3)] = pd;
    }
}

__global__ void avec2_k(const float* __restrict__ h, const float* __restrict__ a_src,
                        const float* __restrict__ a_dst, int n) {
    int w = (blockIdx.x * blockDim.x + threadIdx.x) >> 5;
    int lane = threadIdx.x & 31;
    if (w >= n) return;
    float4 hv = *(const float4*)&h[w * 128 + lane * 4];
    float4 sv = *(const float4*)&a_src[lane * 4];
    float4 dv = *(const float4*)&a_dst[lane * 4];
    float ps = hv.x * sv.x + hv.y * sv.y + hv.z * sv.z + hv.w * sv.w;
    float pd = hv.x * dv.x + hv.y * dv.y + hv.z * dv.z + hv.w * dv.w;
    #pragma unroll
    for (int off = 1; off < 32; off <<= 1) {
        ps += __shfl_xor_sync(FULL, ps, off);
        pd += __shfl_xor_sync(FULL, pd, off);
    }
    if (lane == 0) { g_as2[w] = ps; g_ad2[w] = pd; }
}

// ---------------- GAT aggregation, layer 1 (4 heads), single-pass ----------------
// one warp per dst node; lane owns dims [lane*4, lane*4+4); head = lane>>3.
// no max-subtraction: logits bounded (~|e|<5), softmax is shift-invariant.
__global__ void att1_k(const float* __restrict__ h, const float* __restrict__ b,
                       float* __restrict__ out, int n) {
    __shared__ int   sm_src[8][32];
    __shared__ float sm_p[8][32][4];
    int node = (blockIdx.x * blockDim.x + threadIdx.x) >> 5;
    int lane = threadIdx.x & 31;
    int wslot = (threadIdx.x >> 5) & 7;
    if (node >= n) return;
    int s0 = g_rowptr[node], s1 = g_rowptr[node + 1];

    float4 adv = *(const float4*)&g_ad1[node * 4];
    int head = lane >> 3;
    float4 acc = make_float4(0.f, 0.f, 0.f, 0.f);
    float z0 = 0.f, z1 = 0.f, z2 = 0.f, z3 = 0.f;

    for (int base = s0; base < s1; base += 32) {
        int j = base + lane;
        int s = 0;
        float4 p = make_float4(0.f, 0.f, 0.f, 0.f);
        if (j < s1) {
            s = __ldg(&g_csr[j]);
            float4 asv = *(const float4*)&g_as1[s * 4];
            p.x = __expf(lrelu(asv.x + adv.x));
            p.y = __expf(lrelu(asv.y + adv.y));
            p.z = __expf(lrelu(asv.z + adv.z));
            p.w = __expf(lrelu(asv.w + adv.w));
            z0 += p.x; z1 += p.y; z2 += p.z; z3 += p.w;
        }
        __syncwarp();
        sm_src[wslot][lane] = s;
        *(float4*)&sm_p[wslot][lane][0] = p;
        __syncwarp();
        int cnt = min(32, s1 - base);
        #pragma unroll 4
        for (int jj = 0; jj < cnt; jj++) {
            int   ss = sm_src[wslot][jj];
            float q  = sm_p[wslot][jj][head];
            float4 hv = *(const float4*)&h[ss * 128 + (lane << 2)];
            acc.x += q * hv.x; acc.y += q * hv.y; acc.z += q * hv.z; acc.w += q * hv.w;
        }
    }
    #pragma unroll
    for (int off = 16; off; off >>= 1) {
        z0 += __shfl_xor_sync(FULL, z0, off);
        z1 += __shfl_xor_sync(FULL, z1, off);
        z2 += __shfl_xor_sync(FULL, z2, off);
        z3 += __shfl_xor_sync(FULL, z3, off);
    }
    float z = head == 0 ? z0 : head == 1 ? z1 : head == 2 ? z2 : z3;
    float inv = 1.f / z;
    int c = lane * 4;
    float4 bv = *(const float4*)&b[c];
    float4 o;
    o.x = elu(acc.x * inv + bv.x);
    o.y = elu(acc.y * inv + bv.y);
    o.z = elu(acc.z * inv + bv.z);
    o.w = elu(acc.w * inv + bv.w);
    *(float4*)&out[node * 128 + c] = o;
}

// ---------------- GAT aggregation, layer 2 (1 head), single-pass ----------------
__global__ void att2_k(const float* __restrict__ h, const float* __restrict__ b,
                       float* __restrict__ out, int n) {
    __shared__ float2 sm2[8][32];
    int node = (blockIdx.x * blockDim.x + threadIdx.x) >> 5;
    int lane = threadIdx.x & 31;
    int wslot = (threadIdx.x >> 5) & 7;
    if (node >= n) return;
    int s0 = g_rowptr[node], s1 = g_rowptr[node + 1];

    float ad = g_ad2[node];
    float4 acc = make_float4(0.f, 0.f, 0.f, 0.f);
    float z = 0.f;
    for (int base = s0; base < s1; base += 32) {
        int j = base + lane;
        int s = 0; float p = 0.f;
        if (j < s1) {
            s = __ldg(&g_csr[j]);
            p = __expf(lrelu(g_as2[s] + ad));
            z += p;
        }
        __syncwarp();
        sm2[wslot][lane] = make_float2(__int_as_float(s), p);
        __syncwarp();
        int cnt = min(32, s1 - base);
        #pragma unroll 4
        for (int jj = 0; jj < cnt; jj++) {
            float2 sp = sm2[wslot][jj];
            int   ss = __float_as_int(sp.x);
            float q  = sp.y;
            float4 hv = *(const float4*)&h[ss * 128 + (lane << 2)];
            acc.x += q * hv.x; acc.y += q * hv.y; acc.z += q * hv.z; acc.w += q * hv.w;
        }
    }
    #pragma unroll
    for (int off = 16; off; off >>= 1)
        z += __shfl_xor_sync(FULL, z, off);
    float inv = 1.f / z;
    int c = lane * 4;
    float4 bv = *(const float4*)&b[c];
    float4 o;
    o.x = elu(acc.x * inv + bv.x);
    o.y = elu(acc.y * inv + bv.y);
    o.z = elu(acc.z * inv + bv.z);
    o.w = elu(acc.w * inv + bv.w);
    *(float4*)&out[node * 128 + c] = o;
}

// ---------------- final linear head: [n,128] @ [128,40] + b ----------------
__global__ void head_k(const float* __restrict__ A, const float* __restrict__ W,
                       const float* __restrict__ b, float* __restrict__ out, int n) {
    int i = blockIdx.x * blockDim.x + threadIdx.x;
    if (i >= n * 40) return;
    int row = i / 40, c = i - row * 40;
    const float* xr = &A[row * 128];
    float acc = b[c];
    #pragma unroll 8
    for (int k = 0; k < 128; k++)
        acc += xr[k] * __ldg(&W[k * 40 + c]);
    out[i] = acc;
}

// ---------------- launch ----------------
extern "C" void kernel_launch(void* const* d_in, const int* in_sizes, int n_in,
                              void* d_out, int out_size) {
    const float* x   = (const float*)d_in[0];
    const int*   ei  = (const int*)  d_in[1];
    const float* W1  = (const float*)d_in[2];
    const float* as1 = (const float*)d_in[3];
    const float* ad1 = (const float*)d_in[4];
    const float* b1  = (const float*)d_in[5];
    const float* W2  = (const float*)d_in[6];
    const float* as2 = (const float*)d_in[7];
    const float* ad2 = (const float*)d_in[8];
    const float* b2  = (const float*)d_in[9];
    const float* Wl  = (const float*)d_in[10];
    const float* bl  = (const float*)d_in[11];
    float* out = (float*)d_out;

    const int n = in_sizes[0] / 128;   // 10000
    const int e = in_sizes[1] / 2;     // 640000

    float *h1, *o1, *h2, *o2;
    cudaGetSymbolAddress((void**)&h1, g_h1);
    cudaGetSymbolAddress((void**)&o1, g_o1);
    cudaGetSymbolAddress((void**)&h2, g_h2);
    cudaGetSymbolAddress((void**)&o2, g_o2);

    // CSR build
    init_deg_k<<<(n + 255) / 256, 256>>>(n);
    {
        int q = e >> 2, tail = e & 3;
        int threads = q + tail;
        hist_k<<<(threads + 255) / 256, 256>>>(ei, e);
    }
    scan_k<<<1, 1024>>>(n);
    {
        int q = e >> 2, tail = e & 3;
        int threads = q + tail + n;
        fill_k<<<(threads + 255) / 256, 256>>>(ei, e, n);
    }

    // layer 1
    gemm128_k<<<(n + 31) / 32, 128>>>(x, W1, h1, n);
    avec1_k<<<(n * 32 + 255) / 256, 256>>>(h1, as1, ad1, n);
    att1_k<<<(n * 32 + 255) / 256, 256>>>(h1, b1, o1, n);

    // layer 2
    gemm128_k<<<(n + 31) / 32, 128>>>(o1, W2, h2, n);
    avec2_k<<<(n * 32 + 255) / 256, 256>>>(h2, as2, ad2, n);
    att2_k<<<(n * 32 + 255) / 256, 256>>>(h2, b2, o2, n);

    // head
    head_k<<<(n * 40 + 255) / 256, 256>>>(o2, Wl, bl, out, n);
}

// round 6
// speedup vs baseline: 1.2365x; 1.0462x over previous
#include <cuda_runtime.h>
#include <cuda_fp16.h>
#include <math.h>

#define NN   10000
#define EE   640000
#define TOTE (EE + NN)
#define FULL 0xFFFFFFFFu

// ---------------- scratch (static device globals; no allocation) ----------------
__device__ int   g_deg[NN];          // zero-initialized at load; scan_k re-zeroes after use
__device__ int   g_rowptr[NN + 1];
__device__ int   g_rank[EE];         // per-edge rank within its dst row
__device__ int   g_csr[TOTE];

__device__ __half g_h1h[NN * 128];   // fp16 copy of x @ W1 (gather table)
__device__ float  g_o1[NN * 128];    // elu(gat1)
__device__ __half g_h2h[NN * 128];   // fp16 copy of o1 @ W2
__device__ float  g_o2[NN * 128];    // elu(gat2)

__device__ float g_as1[NN * 4];
__device__ float g_ad1[NN * 4];
__device__ float g_as2[NN];
__device__ float g_ad2[NN];

__device__ __forceinline__ float lrelu(float v) { return v > 0.f ? v : 0.2f * v; }
__device__ __forceinline__ float elu(float v)   { return v > 0.f ? v : (expf(v) - 1.f); }

// ---------------- CSR build ----------------
// one atomic pass: histogram + per-edge rank (the atomicAdd return value)
__global__ void hist_k(const int* __restrict__ ei, int e) {
    int i = blockIdx.x * blockDim.x + threadIdx.x;
    int q = e >> 2;
    if (i < q) {
        int4 d = ((const int4*)(ei + e))[i];
        int4 r;
        r.x = atomicAdd(&g_deg[d.x], 1);
        r.y = atomicAdd(&g_deg[d.y], 1);
        r.z = atomicAdd(&g_deg[d.z], 1);
        r.w = atomicAdd(&g_deg[d.w], 1);
        ((int4*)g_rank)[i] = r;
    } else {
        int r = (q << 2) + (i - q);             // scalar tail (e % 4 edges)
        if (r < e) g_rank[r] = atomicAdd(&g_deg[ei[e + r]], 1);
    }
}

// single-pass block scan over deg+1 (self loop); writes rowptr, self-loop CSR slot,
// and re-zeroes g_deg for the next launch (keeps kernel_launch deterministic).
__global__ void scan_k(int n) {
    __shared__ int wsum[32];
    int t = threadIdx.x, lane = t & 31, wid = t >> 5;
    int items = (n + 1023) >> 10;               // 10 for n=10000
    int base = t * items;
    int v[16];
    int sum = 0;
    #pragma unroll
    for (int i = 0; i < 16; i++) {
        if (i >= items) break;
        int idx = base + i;
        int x = 0;
        if (idx < n) { x = g_deg[idx] + 1; g_deg[idx] = 0; }
        v[i] = sum;                             // thread-local exclusive prefix
        sum += x;
    }
    int incl = sum;
    #pragma unroll
    for (int off = 1; off < 32; off <<= 1) {
        int y = __shfl_up_sync(FULL, incl, off);
        if (lane >= off) incl += y;
    }
    if (lane == 31) wsum[wid] = incl;
    __syncthreads();
    if (wid == 0) {
        int wv = wsum[lane];
        int wi = wv;
        #pragma unroll
        for (int off = 1; off < 32; off <<= 1) {
            int y = __shfl_up_sync(FULL, wi, off);
            if (lane >= off) wi += y;
        }
        wsum[lane] = wi - wv;                   // exclusive warp offsets
    }
    __syncthreads();
    int off = wsum[wid] + incl - sum;           // exclusive offset for this thread
    #pragma unroll
    for (int i = 0; i < 16; i++) {
        if (i >= items) break;
        int idx = base + i;
        if (idx < n) {
            int p = off + v[i];
            g_rowptr[idx] = p;
            g_csr[p] = idx;                     // self loop occupies slot 0
        }
    }
    if (t == 1023) g_rowptr[n] = off + sum;     // grand total
}

// no atomics: position = rowptr[dst] + 1 + rank
__global__ void fill_k(const int* __restrict__ ei, int e) {
    int i = blockIdx.x * blockDim.x + threadIdx.x;
    int q = e >> 2;
    if (i < q) {
        int4 s = ((const int4*)ei)[i];
        int4 d = ((const int4*)(ei + e))[i];
        int4 r = ((const int4*)g_rank)[i];
        g_csr[g_rowptr[d.x] + 1 + r.x] = s.x;
        g_csr[g_rowptr[d.y] + 1 + r.y] = s.y;
        g_csr[g_rowptr[d.z] + 1 + r.z] = s.z;
        g_csr[g_rowptr[d.w] + 1 + r.w] = s.w;
    } else {
        int r = (q << 2) + (i - q);
        if (r < e) g_csr[g_rowptr[ei[e + r]] + 1 + g_rank[r]] = ei[r];
    }
}

// ---- GEMM + fused attention-scalar epilogue: H16 = fp16(A@B), as/ad = (A@B)·a ----
// HEADS=4: as_out/ad_out are [n,4]; HEADS=1: [n].
template<int HEADS>
__global__ void gemm_att_k(const float* __restrict__ A, const float* __restrict__ B,
                           const float* __restrict__ a_src, const float* __restrict__ a_dst,
                           __half* __restrict__ H16,
                           float* __restrict__ as_out, float* __restrict__ ad_out, int n) {
    __shared__ __align__(16) float xs[32][128];
    int row0 = blockIdx.x * 32;
    int t = threadIdx.x;                        // 128 threads; t = output column
    for (int i = t; i < 32 * 128; i += 128) {
        int r = i >> 7, k = i & 127;
        xs[r][k] = (row0 + r < n) ? A[(row0 + r) * 128 + k] : 0.f;
    }
    __syncthreads();
    float acc[32];
    #pragma unroll
    for (int r = 0; r < 32; r++) acc[r] = 0.f;
    for (int k = 0; k < 128; k += 4) {
        float w0 = B[(k + 0) * 128 + t];
        float w1 = B[(k + 1) * 128 + t];
        float w2 = B[(k + 2) * 128 + t];
        float w3 = B[(k + 3) * 128 + t];
        #pragma unroll
        for (int r = 0; r < 32; r++) {
            float4 xv = *(const float4*)&xs[r][k];
            acc[r] += xv.x * w0 + xv.y * w1 + xv.z * w2 + xv.w * w3;
        }
    }
    // fp16 output + stage acc back into smem for the a·h epilogue
    __syncthreads();
    #pragma unroll
    for (int r = 0; r < 32; r++) {
        int row = row0 + r;
        if (row < n) H16[row * 128 + t] = __float2half_rn(acc[r]);
        xs[r][t] = acc[r];
    }
    __syncthreads();
    // 4 warps x 8 rows: per-row dot with a_src / a_dst
    int lane = t & 31, wid = t >> 5;
    float4 sv = *(const float4*)&a_src[lane * 4];
    float4 dv = *(const float4*)&a_dst[lane * 4];
    #pragma unroll
    for (int r8 = 0; r8 < 8; r8++) {
        int r = wid * 8 + r8;
        float4 hv = *(const float4*)&xs[r][lane * 4];
        float ps = hv.x * sv.x + hv.y * sv.y + hv.z * sv.z + hv.w * sv.w;
        float pd = hv.x * dv.x + hv.y * dv.y + hv.z * dv.z + hv.w * dv.w;
        if (HEADS == 4) {
            #pragma unroll
            for (int off = 1; off < 8; off <<= 1) {
                ps += __shfl_xor_sync(FULL, ps, off);
                pd += __shfl_xor_sync(FULL, pd, off);
            }
            int row = row0 + r;
            if (row < n && (lane & 7) == 0) {
                as_out[row * 4 + (lane >> 3)] = ps;
                ad_out[row * 4 + (lane >> 3)] = pd;
            }
        } else {
            #pragma unroll
            for (int off = 1; off < 32; off <<= 1) {
                ps += __shfl_xor_sync(FULL, ps, off);
                pd += __shfl_xor_sync(FULL, pd, off);
            }
            int row = row0 + r;
            if (row < n && lane == 0) { as_out[row] = ps; ad_out[row] = pd; }
        }
    }
}

// ---------------- GAT aggregation, layer 1 (4 heads), fp16 gather ----------------
__global__ void att1_k(const __half* __restrict__ h, const float* __restrict__ b,
                       float* __restrict__ out, int n) {
    __shared__ int   sm_src[8][32];
    __shared__ float sm_p[8][32][4];
    int node = (blockIdx.x * blockDim.x + threadIdx.x) >> 5;
    int lane = threadIdx.x & 31;
    int wslot = (threadIdx.x >> 5) & 7;
    if (node >= n) return;
    int s0 = g_rowptr[node], s1 = g_rowptr[node + 1];

    float4 adv = *(const float4*)&g_ad1[node * 4];
    int head = lane >> 3;
    float4 acc = make_float4(0.f, 0.f, 0.f, 0.f);
    float z0 = 0.f, z1 = 0.f, z2 = 0.f, z3 = 0.f;

    for (int base = s0; base < s1; base += 32) {
        int j = base + lane;
        int s = 0;
        float4 p = make_float4(0.f, 0.f, 0.f, 0.f);
        if (j < s1) {
            s = __ldg(&g_csr[j]);
            float4 asv = *(const float4*)&g_as1[s * 4];
            p.x = __expf(lrelu(asv.x + adv.x));
            p.y = __expf(lrelu(asv.y + adv.y));
            p.z = __expf(lrelu(asv.z + adv.z));
            p.w = __expf(lrelu(asv.w + adv.w));
            z0 += p.x; z1 += p.y; z2 += p.z; z3 += p.w;
        }
        __syncwarp();
        sm_src[wslot][lane] = s;
        *(float4*)&sm_p[wslot][lane][0] = p;
        __syncwarp();
        int cnt = min(32, s1 - base);
        #pragma unroll 4
        for (int jj = 0; jj < cnt; jj++) {
            int   ss = sm_src[wslot][jj];
            float q  = sm_p[wslot][jj][head];
            uint2 u = *(const uint2*)&h[ss * 128 + (lane << 2)];
            float2 f01 = __half22float2(*reinterpret_cast<__half2*>(&u.x));
            float2 f23 = __half22float2(*reinterpret_cast<__half2*>(&u.y));
            acc.x += q * f01.x; acc.y += q * f01.y;
            acc.z += q * f23.x; acc.w += q * f23.y;
        }
    }
    #pragma unroll
    for (int off = 16; off; off >>= 1) {
        z0 += __shfl_xor_sync(FULL, z0, off);
        z1 += __shfl_xor_sync(FULL, z1, off);
        z2 += __shfl_xor_sync(FULL, z2, off);
        z3 += __shfl_xor_sync(FULL, z3, off);
    }
    float z = head == 0 ? z0 : head == 1 ? z1 : head == 2 ? z2 : z3;
    float inv = 1.f / z;
    int c = lane * 4;
    float4 bv = *(const float4*)&b[c];
    float4 o;
    o.x = elu(acc.x * inv + bv.x);
    o.y = elu(acc.y * inv + bv.y);
    o.z = elu(acc.z * inv + bv.z);
    o.w = elu(acc.w * inv + bv.w);
    *(float4*)&out[node * 128 + c] = o;
}

// ---------------- GAT aggregation, layer 2 (1 head), fp16 gather ----------------
__global__ void att2_k(const __half* __restrict__ h, const float* __restrict__ b,
                       float* __restrict__ out, int n) {
    __shared__ float2 sm2[8][32];
    int node = (blockIdx.x * blockDim.x + threadIdx.x) >> 5;
    int lane = threadIdx.x & 31;
    int wslot = (threadIdx.x >> 5) & 7;
    if (node >= n) return;
    int s0 = g_rowptr[node], s1 = g_rowptr[node + 1];

    float ad = g_ad2[node];
    float4 acc = make_float4(0.f, 0.f, 0.f, 0.f);
    float z = 0.f;
    for (int base = s0; base < s1; base += 32) {
        int j = base + lane;
        int s = 0; float p = 0.f;
        if (j < s1) {
            s = __ldg(&g_csr[j]);
            p = __expf(lrelu(g_as2[s] + ad));
            z += p;
        }
        __syncwarp();
        sm2[wslot][lane] = make_float2(__int_as_float(s), p);
        __syncwarp();
        int cnt = min(32, s1 - base);
        #pragma unroll 4
        for (int jj = 0; jj < cnt; jj++) {
            float2 sp = sm2[wslot][jj];
            int   ss = __float_as_int(sp.x);
            float q  = sp.y;
            uint2 u = *(const uint2*)&h[ss * 128 + (lane << 2)];
            float2 f01 = __half22float2(*reinterpret_cast<__half2*>(&u.x));
            float2 f23 = __half22float2(*reinterpret_cast<__half2*>(&u.y));
            acc.x += q * f01.x; acc.y += q * f01.y;
            acc.z += q * f23.x; acc.w += q * f23.y;
        }
    }
    #pragma unroll
    for (int off = 16; off; off >>= 1)
        z += __shfl_xor_sync(FULL, z, off);
    float inv = 1.f / z;
    int c = lane * 4;
    float4 bv = *(const float4*)&b[c];
    float4 o;
    o.x = elu(acc.x * inv + bv.x);
    o.y = elu(acc.y * inv + bv.y);
    o.z = elu(acc.z * inv + bv.z);
    o.w = elu(acc.w * inv + bv.w);
    *(float4*)&out[node * 128 + c] = o;
}

// ---------------- final linear head: [n,128] @ [128,40] + b ----------------
__global__ void head_k(const float* __restrict__ A, const float* __restrict__ W,
                       const float* __restrict__ b, float* __restrict__ out, int n) {
    int i = blockIdx.x * blockDim.x + threadIdx.x;
    if (i >= n * 40) return;
    int row = i / 40, c = i - row * 40;
    const float* xr = &A[row * 128];
    float acc = b[c];
    #pragma unroll 8
    for (int k = 0; k < 128; k++)
        acc += xr[k] * __ldg(&W[k * 40 + c]);
    out[i] = acc;
}

// ---------------- launch ----------------
extern "C" void kernel_launch(void* const* d_in, const int* in_sizes, int n_in,
                              void* d_out, int out_size) {
    const float* x   = (const float*)d_in[0];
    const int*   ei  = (const int*)  d_in[1];
    const float* W1  = (const float*)d_in[2];
    const float* as1 = (const float*)d_in[3];
    const float* ad1 = (const float*)d_in[4];
    const float* b1  = (const float*)d_in[5];
    const float* W2  = (const float*)d_in[6];
    const float* as2 = (const float*)d_in[7];
    const float* ad2 = (const float*)d_in[8];
    const float* b2  = (const float*)d_in[9];
    const float* Wl  = (const float*)d_in[10];
    const float* bl  = (const float*)d_in[11];
    float* out = (float*)d_out;

    const int n = in_sizes[0] / 128;   // 10000
    const int e = in_sizes[1] / 2;     // 640000

    __half *h1h, *h2h;
    float *o1, *o2, *pas1, *pad1, *pas2, *pad2;
    cudaGetSymbolAddress((void**)&h1h, g_h1h);
    cudaGetSymbolAddress((void**)&h2h, g_h2h);
    cudaGetSymbolAddress((void**)&o1,  g_o1);
    cudaGetSymbolAddress((void**)&o2,  g_o2);
    cudaGetSymbolAddress((void**)&pas1, g_as1);
    cudaGetSymbolAddress((void**)&pad1, g_ad1);
    cudaGetSymbolAddress((void**)&pas2, g_as2);
    cudaGetSymbolAddress((void**)&pad2, g_ad2);

    int q = e >> 2, tail = e & 3;
    int ethreads = q + tail;

    // CSR build (one atomic pass; rank-based fill, no second atomic round)
    hist_k<<<(ethreads + 255) / 256, 256>>>(ei, e);
    scan_k<<<1, 1024>>>(n);
    fill_k<<<(ethreads + 255) / 256, 256>>>(ei, e);

    // layer 1
    gemm_att_k<4><<<(n + 31) / 32, 128>>>(x, W1, as1, ad1, h1h, pas1, pad1, n);
    att1_k<<<(n * 32 + 255) / 256, 256>>>(h1h, b1, o1, n);

    // layer 2
    gemm_att_k<1><<<(n + 31) / 32, 128>>>(o1, W2, as2, ad2, h2h, pas2, pad2, n);
    att2_k<<<(n * 32 + 255) / 256, 256>>>(h2h, b2, o2, n);

    // head
    head_k<<<(n * 40 + 255) / 256, 256>>>(o2, Wl, bl, out, n);
}

// round 7
// speedup vs baseline: 1.3108x; 1.0601x over previous
#include <cuda_runtime.h>
#include <cuda_fp16.h>
#include <math.h>

#define NN   10000
#define EE   640000
#define TOTE (EE + NN)
#define FULL 0xFFFFFFFFu

// ---------------- scratch (static device globals; no allocation) ----------------
__device__ int   g_deg[NN];          // zero-initialized at load; scan_k re-zeroes after use
__device__ int   g_rowptr[NN + 1];
__device__ int   g_rank[EE];         // per-edge rank within its dst row
__device__ int   g_csr[TOTE];

__device__ __half g_h1h[NN * 128];   // fp16 copy of x @ W1 (gather table)
__device__ float  g_o1[NN * 128];    // elu(gat1)
__device__ __half g_h2h[NN * 128];   // fp16 copy of o1 @ W2
__device__ float  g_o2[NN * 128];    // elu(gat2)

__device__ float g_as1[NN * 4];
__device__ float g_ad1[NN * 4];
__device__ float g_as2[NN];
__device__ float g_ad2[NN];

__device__ __forceinline__ float lrelu(float v) { return v > 0.f ? v : 0.2f * v; }
__device__ __forceinline__ float elu(float v)   { return v > 0.f ? v : (expf(v) - 1.f); }

// ---------------- CSR build ----------------
// one atomic pass: histogram + per-edge rank (the atomicAdd return value)
__global__ void hist_k(const int* __restrict__ ei, int e) {
    int i = blockIdx.x * blockDim.x + threadIdx.x;
    int q = e >> 2;
    if (i < q) {
        int4 d = ((const int4*)(ei + e))[i];
        int4 r;
        r.x = atomicAdd(&g_deg[d.x], 1);
        r.y = atomicAdd(&g_deg[d.y], 1);
        r.z = atomicAdd(&g_deg[d.z], 1);
        r.w = atomicAdd(&g_deg[d.w], 1);
        ((int4*)g_rank)[i] = r;
    } else {
        int r = (q << 2) + (i - q);             // scalar tail (e % 4 edges)
        if (r < e) g_rank[r] = atomicAdd(&g_deg[ei[e + r]], 1);
    }
}

// single-pass block scan over deg+1 (self loop); writes rowptr, self-loop CSR slot,
// and re-zeroes g_deg for the next launch (keeps kernel_launch deterministic).
__global__ void scan_k(int n) {
    __shared__ int wsum[32];
    int t = threadIdx.x, lane = t & 31, wid = t >> 5;
    int items = (n + 1023) >> 10;               // 10 for n=10000
    int base = t * items;
    int v[16];
    int sum = 0;
    #pragma unroll
    for (int i = 0; i < 16; i++) {
        if (i >= items) break;
        int idx = base + i;
        int x = 0;
        if (idx < n) { x = g_deg[idx] + 1; g_deg[idx] = 0; }
        v[i] = sum;                             // thread-local exclusive prefix
        sum += x;
    }
    int incl = sum;
    #pragma unroll
    for (int off = 1; off < 32; off <<= 1) {
        int y = __shfl_up_sync(FULL, incl, off);
        if (lane >= off) incl += y;
    }
    if (lane == 31) wsum[wid] = incl;
    __syncthreads();
    if (wid == 0) {
        int wv = wsum[lane];
        int wi = wv;
        #pragma unroll
        for (int off = 1; off < 32; off <<= 1) {
            int y = __shfl_up_sync(FULL, wi, off);
            if (lane >= off) wi += y;
        }
        wsum[lane] = wi - wv;                   // exclusive warp offsets
    }
    __syncthreads();
    int off = wsum[wid] + incl - sum;           // exclusive offset for this thread
    #pragma unroll
    for (int i = 0; i < 16; i++) {
        if (i >= items) break;
        int idx = base + i;
        if (idx < n) {
            int p = off + v[i];
            g_rowptr[idx] = p;
            g_csr[p] = idx;                     // self loop occupies slot 0
        }
    }
    if (t == 1023) g_rowptr[n] = off + sum;     // grand total
}

// no atomics: position = rowptr[dst] + 1 + rank
__global__ void fill_k(const int* __restrict__ ei, int e) {
    int i = blockIdx.x * blockDim.x + threadIdx.x;
    int q = e >> 2;
    if (i < q) {
        int4 s = ((const int4*)ei)[i];
        int4 d = ((const int4*)(ei + e))[i];
        int4 r = ((const int4*)g_rank)[i];
        g_csr[g_rowptr[d.x] + 1 + r.x] = s.x;
        g_csr[g_rowptr[d.y] + 1 + r.y] = s.y;
        g_csr[g_rowptr[d.z] + 1 + r.z] = s.z;
        g_csr[g_rowptr[d.w] + 1 + r.w] = s.w;
    } else {
        int r = (q << 2) + (i - q);
        if (r < e) g_csr[g_rowptr[ei[e + r]] + 1 + g_rank[r]] = ei[r];
    }
}

// ---- GEMM + fused attention-scalar epilogue: H16 = fp16(A@B), as/ad = (A@B)·a ----
// 8 rows per block (grid ~1250) for occupancy; 128 threads, t = output column.
// HEADS=4: as_out/ad_out are [n,4]; HEADS=1: [n].
#define GROWS 8
template<int HEADS>
__global__ void gemm_att_k(const float* __restrict__ A, const float* __restrict__ B,
                           const float* __restrict__ a_src, const float* __restrict__ a_dst,
                           __half* __restrict__ H16,
                           float* __restrict__ as_out, float* __restrict__ ad_out, int n) {
    __shared__ __align__(16) float xs[GROWS][128];
    int row0 = blockIdx.x * GROWS;
    int t = threadIdx.x;                        // 128 threads; t = output column
    for (int i = t; i < GROWS * 128; i += 128) {
        int r = i >> 7, k = i & 127;
        xs[r][k] = (row0 + r < n) ? A[(row0 + r) * 128 + k] : 0.f;
    }
    __syncthreads();
    float acc[GROWS];
    #pragma unroll
    for (int r = 0; r < GROWS; r++) acc[r] = 0.f;
    for (int k = 0; k < 128; k += 4) {
        float w0 = B[(k + 0) * 128 + t];
        float w1 = B[(k + 1) * 128 + t];
        float w2 = B[(k + 2) * 128 + t];
        float w3 = B[(k + 3) * 128 + t];
        #pragma unroll
        for (int r = 0; r < GROWS; r++) {
            float4 xv = *(const float4*)&xs[r][k];
            acc[r] += xv.x * w0 + xv.y * w1 + xv.z * w2 + xv.w * w3;
        }
    }
    // fp16 output + stage acc back into smem for the a·h epilogue
    __syncthreads();
    #pragma unroll
    for (int r = 0; r < GROWS; r++) {
        int row = row0 + r;
        if (row < n) H16[row * 128 + t] = __float2half_rn(acc[r]);
        xs[r][t] = acc[r];
    }
    __syncthreads();
    // 4 warps x 2 rows: per-row dot with a_src / a_dst
    int lane = t & 31, wid = t >> 5;
    float4 sv = *(const float4*)&a_src[lane * 4];
    float4 dv = *(const float4*)&a_dst[lane * 4];
    #pragma unroll
    for (int r2 = 0; r2 < GROWS / 4; r2++) {
        int r = wid * (GROWS / 4) + r2;
        float4 hv = *(const float4*)&xs[r][lane * 4];
        float ps = hv.x * sv.x + hv.y * sv.y + hv.z * sv.z + hv.w * sv.w;
        float pd = hv.x * dv.x + hv.y * dv.y + hv.z * dv.z + hv.w * dv.w;
        if (HEADS == 4) {
            #pragma unroll
            for (int off = 1; off < 8; off <<= 1) {
                ps += __shfl_xor_sync(FULL, ps, off);
                pd += __shfl_xor_sync(FULL, pd, off);
            }
            int row = row0 + r;
            if (row < n && (lane & 7) == 0) {
                as_out[row * 4 + (lane >> 3)] = ps;
                ad_out[row * 4 + (lane >> 3)] = pd;
            }
        } else {
            #pragma unroll
            for (int off = 1; off < 32; off <<= 1) {
                ps += __shfl_xor_sync(FULL, ps, off);
                pd += __shfl_xor_sync(FULL, pd, off);
            }
            int row = row0 + r;
            if (row < n && lane == 0) { as_out[row] = ps; ad_out[row] = pd; }
        }
    }
}

// ---------------- GAT aggregation, layer 1 (4 heads), fp16 gather ----------------
__global__ void att1_k(const __half* __restrict__ h, const float* __restrict__ b,
                       float* __restrict__ out, int n) {
    __shared__ int   sm_src[8][32];
    __shared__ float sm_p[8][32][4];
    int node = (blockIdx.x * blockDim.x + threadIdx.x) >> 5;
    int lane = threadIdx.x & 31;
    int wslot = (threadIdx.x >> 5) & 7;
    if (node >= n) return;
    int s0 = g_rowptr[node], s1 = g_rowptr[node + 1];

    float4 adv = *(const float4*)&g_ad1[node * 4];
    int head = lane >> 3;
    float4 acc = make_float4(0.f, 0.f, 0.f, 0.f);
    float z0 = 0.f, z1 = 0.f, z2 = 0.f, z3 = 0.f;

    for (int base = s0; base < s1; base += 32) {
        int j = base + lane;
        int s = 0;
        float4 p = make_float4(0.f, 0.f, 0.f, 0.f);
        if (j < s1) {
            s = __ldg(&g_csr[j]);
            float4 asv = *(const float4*)&g_as1[s * 4];
            p.x = __expf(lrelu(asv.x + adv.x));
            p.y = __expf(lrelu(asv.y + adv.y));
            p.z = __expf(lrelu(asv.z + adv.z));
            p.w = __expf(lrelu(asv.w + adv.w));
            z0 += p.x; z1 += p.y; z2 += p.z; z3 += p.w;
        }
        __syncwarp();
        sm_src[wslot][lane] = s;
        *(float4*)&sm_p[wslot][lane][0] = p;
        __syncwarp();
        int cnt = min(32, s1 - base);
        #pragma unroll 4
        for (int jj = 0; jj < cnt; jj++) {
            int   ss = sm_src[wslot][jj];
            float q  = sm_p[wslot][jj][head];
            uint2 u = *(const uint2*)&h[ss * 128 + (lane << 2)];
            float2 f01 = __half22float2(*reinterpret_cast<__half2*>(&u.x));
            float2 f23 = __half22float2(*reinterpret_cast<__half2*>(&u.y));
            acc.x += q * f01.x; acc.y += q * f01.y;
            acc.z += q * f23.x; acc.w += q * f23.y;
        }
    }
    #pragma unroll
    for (int off = 16; off; off >>= 1) {
        z0 += __shfl_xor_sync(FULL, z0, off);
        z1 += __shfl_xor_sync(FULL, z1, off);
        z2 += __shfl_xor_sync(FULL, z2, off);
        z3 += __shfl_xor_sync(FULL, z3, off);
    }
    float z = head == 0 ? z0 : head == 1 ? z1 : head == 2 ? z2 : z3;
    float inv = 1.f / z;
    int c = lane * 4;
    float4 bv = *(const float4*)&b[c];
    float4 o;
    o.x = elu(acc.x * inv + bv.x);
    o.y = elu(acc.y * inv + bv.y);
    o.z = elu(acc.z * inv + bv.z);
    o.w = elu(acc.w * inv + bv.w);
    *(float4*)&out[node * 128 + c] = o;
}

// ---------------- GAT aggregation, layer 2 (1 head), fp16 gather ----------------
__global__ void att2_k(const __half* __restrict__ h, const float* __restrict__ b,
                       float* __restrict__ out, int n) {
    __shared__ float2 sm2[8][32];
    int node = (blockIdx.x * blockDim.x + threadIdx.x) >> 5;
    int lane = threadIdx.x & 31;
    int wslot = (threadIdx.x >> 5) & 7;
    if (node >= n) return;
    int s0 = g_rowptr[node], s1 = g_rowptr[node + 1];

    float ad = g_ad2[node];
    float4 acc = make_float4(0.f, 0.f, 0.f, 0.f);
    float z = 0.f;
    for (int base = s0; base < s1; base += 32) {
        int j = base + lane;
        int s = 0; float p = 0.f;
        if (j < s1) {
            s = __ldg(&g_csr[j]);
            p = __expf(lrelu(g_as2[s] + ad));
            z += p;
        }
        __syncwarp();
        sm2[wslot][lane] = make_float2(__int_as_float(s), p);
        __syncwarp();
        int cnt = min(32, s1 - base);
        #pragma unroll 4
        for (int jj = 0; jj < cnt; jj++) {
            float2 sp = sm2[wslot][jj];
            int   ss = __float_as_int(sp.x);
            float q  = sp.y;
            uint2 u = *(const uint2*)&h[ss * 128 + (lane << 2)];
            float2 f01 = __half22float2(*reinterpret_cast<__half2*>(&u.x));
            float2 f23 = __half22float2(*reinterpret_cast<__half2*>(&u.y));
            acc.x += q * f01.x; acc.y += q * f01.y;
            acc.z += q * f23.x; acc.w += q * f23.y;
        }
    }
    #pragma unroll
    for (int off = 16; off; off >>= 1)
        z += __shfl_xor_sync(FULL, z, off);
    float inv = 1.f / z;
    int c = lane * 4;
    float4 bv = *(const float4*)&b[c];
    float4 o;
    o.x = elu(acc.x * inv + bv.x);
    o.y = elu(acc.y * inv + bv.y);
    o.z = elu(acc.z * inv + bv.z);
    o.w = elu(acc.w * inv + bv.w);
    *(float4*)&out[node * 128 + c] = o;
}

// ---------------- final linear head: [n,128] @ [128,40] + b ----------------
__global__ void head_k(const float* __restrict__ A, const float* __restrict__ W,
                       const float* __restrict__ b, float* __restrict__ out, int n) {
    int i = blockIdx.x * blockDim.x + threadIdx.x;
    if (i >= n * 40) return;
    int row = i / 40, c = i - row * 40;
    const float* xr = &A[row * 128];
    float acc = b[c];
    #pragma unroll 8
    for (int k = 0; k < 128; k++)
        acc += xr[k] * __ldg(&W[k * 40 + c]);
    out[i] = acc;
}

// ---------------- launch ----------------
extern "C" void kernel_launch(void* const* d_in, const int* in_sizes, int n_in,
                              void* d_out, int out_size) {
    const float* x   = (const float*)d_in[0];
    const int*   ei  = (const int*)  d_in[1];
    const float* W1  = (const float*)d_in[2];
    const float* as1 = (const float*)d_in[3];
    const float* ad1 = (const float*)d_in[4];
    const float* b1  = (const float*)d_in[5];
    const float* W2  = (const float*)d_in[6];
    const float* as2 = (const float*)d_in[7];
    const float* ad2 = (const float*)d_in[8];
    const float* b2  = (const float*)d_in[9];
    const float* Wl  = (const float*)d_in[10];
    const float* bl  = (const float*)d_in[11];
    float* out = (float*)d_out;

    const int n = in_sizes[0] / 128;   // 10000
    const int e = in_sizes[1] / 2;     // 640000

    __half *h1h, *h2h;
    float *o1, *o2, *pas1, *pad1, *pas2, *pad2;
    cudaGetSymbolAddress((void**)&h1h, g_h1h);
    cudaGetSymbolAddress((void**)&h2h, g_h2h);
    cudaGetSymbolAddress((void**)&o1,  g_o1);
    cudaGetSymbolAddress((void**)&o2,  g_o2);
    cudaGetSymbolAddress((void**)&pas1, g_as1);
    cudaGetSymbolAddress((void**)&pad1, g_ad1);
    cudaGetSymbolAddress((void**)&pas2, g_as2);
    cudaGetSymbolAddress((void**)&pad2, g_ad2);

    int q = e >> 2, tail = e & 3;
    int ethreads = q + tail;

    // CSR build (one atomic pass; rank-based fill, no second atomic round)
    hist_k<<<(ethreads + 255) / 256, 256>>>(ei, e);
    scan_k<<<1, 1024>>>(n);
    fill_k<<<(ethreads + 255) / 256, 256>>>(ei, e);

    // layer 1
    gemm_att_k<4><<<(n + GROWS - 1) / GROWS, 128>>>(x, W1, as1, ad1, h1h, pas1, pad1, n);
    att1_k<<<(n * 32 + 255) / 256, 256>>>(h1h, b1, o1, n);

    // layer 2
    gemm_att_k<1><<<(n + GROWS - 1) / GROWS, 128>>>(o1, W2, as2, ad2, h2h, pas2, pad2, n);
    att2_k<<<(n * 32 + 255) / 256, 256>>>(h2h, b2, o2, n);

    // head
    head_k<<<(n * 40 + 255) / 256, 256>>>(o2, Wl, bl, out, n);
}

// round 8
// speedup vs baseline: 1.4196x; 1.0830x over previous
#include <cuda_runtime.h>
#include <cuda_fp16.h>
#include <math.h>

#define NN   10000
#define EE   640000
#define TOTE (EE + NN)
#define FULL 0xFFFFFFFFu

// ---------------- scratch (static device globals; no allocation) ----------------
__device__ int   g_deg[NN];          // zero-initialized at load; scan_k re-zeroes after use
__device__ int   g_rowptr[NN + 1];
__device__ int   g_rank[EE];         // per-edge rank within its dst row
__device__ int   g_csr[TOTE];

__device__ __half g_B1t[128 * 128];  // fp16 W1, transposed: Bt[c*128+k] = W[k*128+c]
__device__ __half g_B2t[128 * 128];  // fp16 W2, transposed
__device__ __half g_h1h[NN * 128];   // fp16 h1 = x @ W1 (gather table)
__device__ __half g_o1h[NN * 128];   // fp16 elu(gat1) -> input of gemm2
__device__ __half g_h2h[NN * 128];   // fp16 h2 = o1 @ W2 (gather table)
__device__ float  g_o2[NN * 128];    // fp32 elu(gat2) -> input of head

__device__ float g_as1[NN * 4];
__device__ float g_ad1[NN * 4];
__device__ float g_as2[NN];
__device__ float g_ad2[NN];

__device__ __forceinline__ float lrelu(float v) { return v > 0.f ? v : 0.2f * v; }
__device__ __forceinline__ float elu(float v)   { return v > 0.f ? v : (expf(v) - 1.f); }

// ---------------- CSR build ----------------
// one atomic pass: histogram + per-edge rank (the atomicAdd return value)
__global__ void hist_k(const int* __restrict__ ei, int e) {
    int i = blockIdx.x * blockDim.x + threadIdx.x;
    int q = e >> 2;
    if (i < q) {
        int4 d = ((const int4*)(ei + e))[i];
        int4 r;
        r.x = atomicAdd(&g_deg[d.x], 1);
        r.y = atomicAdd(&g_deg[d.y], 1);
        r.z = atomicAdd(&g_deg[d.z], 1);
        r.w = atomicAdd(&g_deg[d.w], 1);
        ((int4*)g_rank)[i] = r;
    } else {
        int r = (q << 2) + (i - q);             // scalar tail (e % 4 edges)
        if (r < e) g_rank[r] = atomicAdd(&g_deg[ei[e + r]], 1);
    }
}

// single-pass block scan over deg+1 (self loop); writes rowptr, self-loop CSR slot,
// and re-zeroes g_deg for the next launch (keeps kernel_launch deterministic).
__global__ void scan_k(int n) {
    __shared__ int wsum[32];
    int t = threadIdx.x, lane = t & 31, wid = t >> 5;
    int items = (n + 1023) >> 10;               // 10 for n=10000
    int base = t * items;
    int v[16];
    int sum = 0;
    #pragma unroll
    for (int i = 0; i < 16; i++) {
        if (i >= items) break;
        int idx = base + i;
        int x = 0;
        if (idx < n) { x = g_deg[idx] + 1; g_deg[idx] = 0; }
        v[i] = sum;                             // thread-local exclusive prefix
        sum += x;
    }
    int incl = sum;
    #pragma unroll
    for (int off = 1; off < 32; off <<= 1) {
        int y = __shfl_up_sync(FULL, incl, off);
        if (lane >= off) incl += y;
    }
    if (lane == 31) wsum[wid] = incl;
    __syncthreads();
    if (wid == 0) {
        int wv = wsum[lane];
        int wi = wv;
        #pragma unroll
        for (int off = 1; off < 32; off <<= 1) {
            int y = __shfl_up_sync(FULL, wi, off);
            if (lane >= off) wi += y;
        }
        wsum[lane] = wi - wv;                   // exclusive warp offsets
    }
    __syncthreads();
    int off = wsum[wid] + incl - sum;           // exclusive offset for this thread
    #pragma unroll
    for (int i = 0; i < 16; i++) {
        if (i >= items) break;
        int idx = base + i;
        if (idx < n) {
            int p = off + v[i];
            g_rowptr[idx] = p;
            g_csr[p] = idx;                     // self loop occupies slot 0
        }
    }
    if (t == 1023) g_rowptr[n] = off + sum;     // grand total
}

// no atomics: position = rowptr[dst] + 1 + rank
__global__ void fill_k(const int* __restrict__ ei, int e) {
    int i = blockIdx.x * blockDim.x + threadIdx.x;
    int q = e >> 2;
    if (i < q) {
        int4 s = ((const int4*)ei)[i];
        int4 d = ((const int4*)(ei + e))[i];
        int4 r = ((const int4*)g_rank)[i];
        g_csr[g_rowptr[d.x] + 1 + r.x] = s.x;
        g_csr[g_rowptr[d.y] + 1 + r.y] = s.y;
        g_csr[g_rowptr[d.z] + 1 + r.z] = s.z;
        g_csr[g_rowptr[d.w] + 1 + r.w] = s.w;
    } else {
        int r = (q << 2) + (i - q);
        if (r < e) g_csr[g_rowptr[ei[e + r]] + 1 + g_rank[r]] = ei[r];
    }
}

// ---- weight convert: Bt[c*128+k] = fp16(W[k*128+c])  (k-contiguous for mma B frags) ----
__global__ void wcvt_k(const float* __restrict__ W, __half* __restrict__ Bt) {
    int i = blockIdx.x * blockDim.x + threadIdx.x;   // 16384
    int c = i >> 7, k = i & 127;
    Bt[(c << 7) + k] = __float2half_rn(W[(k << 7) + c]);
}

// ---- tensor-core GEMM + fused attention-scalar epilogue ----
// block = 128 threads (4 warps), tile 16 rows x 128 cols; warp w owns cols [32w,32w+32).
// mma.m16n8k16 fp16 in / fp32 accum. AFP32: stage-convert A; else A already fp16.
// HEADS=4: as_out/ad_out are [n,4]; HEADS=1: [n].
template<int HEADS, bool AFP32>
__global__ void gemm16_k(const void* __restrict__ Avoid, const __half* __restrict__ Bt,
                         const float* __restrict__ a_src, const float* __restrict__ a_dst,
                         __half* __restrict__ H16,
                         float* __restrict__ as_out, float* __restrict__ ad_out, int n) {
    __shared__ __align__(16) __half As[16][136];   // pad 8 halves: conflict-free frag loads
    __shared__ __align__(16) float  xs[16][128];   // fp32 result staging for a·h epilogue
    int row0 = blockIdx.x * 16;
    int t = threadIdx.x, lane = t & 31, w = t >> 5;

    // stage A (16 rows) as fp16
    for (int i = t; i < 16 * 32; i += 128) {
        int r = i >> 5, k4 = (i & 31) << 2;
        int row = row0 + r;
        if (AFP32) {
            const float* Af = (const float*)Avoid;
            float4 v = (row < n) ? *(const float4*)&Af[row * 128 + k4]
                                 : make_float4(0.f, 0.f, 0.f, 0.f);
            *(__half2*)&As[r][k4]     = __floats2half2_rn(v.x, v.y);
            *(__half2*)&As[r][k4 + 2] = __floats2half2_rn(v.z, v.w);
        } else {
            const __half* Ah = (const __half*)Avoid;
            uint2 v = (row < n) ? *(const uint2*)&Ah[row * 128 + k4] : make_uint2(0u, 0u);
            *(uint2*)&As[r][k4] = v;
        }
    }
    __syncthreads();

    int g = lane >> 2, t4 = lane & 3;
    float c[4][4];
    #pragma unroll
    for (int nt = 0; nt < 4; nt++)
        #pragma unroll
        for (int i = 0; i < 4; i++) c[nt][i] = 0.f;

    #pragma unroll
    for (int kc = 0; kc < 128; kc += 16) {
        unsigned a0 = *(const unsigned*)&As[g][kc + t4 * 2];
        unsigned a1 = *(const unsigned*)&As[g + 8][kc + t4 * 2];
        unsigned a2 = *(const unsigned*)&As[g][kc + 8 + t4 * 2];
        unsigned a3 = *(const unsigned*)&As[g + 8][kc + 8 + t4 * 2];
        #pragma unroll
        for (int nt = 0; nt < 4; nt++) {
            int col = (w * 4 + nt) * 8 + g;            // B-frag col = groupID
            unsigned b0 = *(const unsigned*)&Bt[col * 128 + kc + t4 * 2];
            unsigned b1 = *(const unsigned*)&Bt[col * 128 + kc + 8 + t4 * 2];
            asm volatile(
                "mma.sync.aligned.m16n8k16.row.col.f32.f16.f16.f32 "
                "{%0,%1,%2,%3}, {%4,%5,%6,%7}, {%8,%9}, {%0,%1,%2,%3};"
                : "+f"(c[nt][0]), "+f"(c[nt][1]), "+f"(c[nt][2]), "+f"(c[nt][3])
                : "r"(a0), "r"(a1), "r"(a2), "r"(a3), "r"(b0), "r"(b1));
        }
    }

    __syncthreads();   // before reusing xs
    #pragma unroll
    for (int nt = 0; nt < 4; nt++) {
        int colb = (w * 4 + nt) * 8 + t4 * 2;          // C-frag col = t4*2
        int r0 = row0 + g, r1 = row0 + g + 8;
        if (r0 < n) {
            *(__half2*)&H16[r0 * 128 + colb] = __floats2half2_rn(c[nt][0], c[nt][1]);
            xs[g][colb]     = c[nt][0];
            xs[g][colb + 1] = c[nt][1];
        }
        if (r1 < n) {
            *(__half2*)&H16[r1 * 128 + colb] = __floats2half2_rn(c[nt][2], c[nt][3]);
            xs[g + 8][colb]     = c[nt][2];
            xs[g + 8][colb + 1] = c[nt][3];
        }
    }
    __syncthreads();

    // a·h epilogue: 4 warps x 4 rows
    float4 sv = *(const float4*)&a_src[lane * 4];
    float4 dv = *(const float4*)&a_dst[lane * 4];
    #pragma unroll
    for (int r4 = 0; r4 < 4; r4++) {
        int r = w * 4 + r4;
        float4 hv = *(const float4*)&xs[r][lane * 4];
        float ps = hv.x * sv.x + hv.y * sv.y + hv.z * sv.z + hv.w * sv.w;
        float pd = hv.x * dv.x + hv.y * dv.y + hv.z * dv.z + hv.w * dv.w;
        if (HEADS == 4) {
            #pragma unroll
            for (int off = 1; off < 8; off <<= 1) {
                ps += __shfl_xor_sync(FULL, ps, off);
                pd += __shfl_xor_sync(FULL, pd, off);
            }
            int row = row0 + r;
            if (row < n && (lane & 7) == 0) {
                as_out[row * 4 + (lane >> 3)] = ps;
                ad_out[row * 4 + (lane >> 3)] = pd;
            }
        } else {
            #pragma unroll
            for (int off = 1; off < 32; off <<= 1) {
                ps += __shfl_xor_sync(FULL, ps, off);
                pd += __shfl_xor_sync(FULL, pd, off);
            }
            int row = row0 + r;
            if (row < n && lane == 0) { as_out[row] = ps; ad_out[row] = pd; }
        }
    }
}

// ---------------- GAT aggregation, layer 1 (4 heads), fp16 gather, fp16 out ----------------
__global__ void att1_k(const __half* __restrict__ h, const float* __restrict__ b,
                       __half* __restrict__ out, int n) {
    __shared__ int   sm_src[8][32];
    __shared__ float sm_p[8][32][4];
    int node = (blockIdx.x * blockDim.x + threadIdx.x) >> 5;
    int lane = threadIdx.x & 31;
    int wslot = (threadIdx.x >> 5) & 7;
    if (node >= n) return;
    int s0 = g_rowptr[node], s1 = g_rowptr[node + 1];

    float4 adv = *(const float4*)&g_ad1[node * 4];
    int head = lane >> 3;
    float4 acc = make_float4(0.f, 0.f, 0.f, 0.f);
    float z0 = 0.f, z1 = 0.f, z2 = 0.f, z3 = 0.f;

    for (int base = s0; base < s1; base += 32) {
        int j = base + lane;
        int s = 0;
        float4 p = make_float4(0.f, 0.f, 0.f, 0.f);
        if (j < s1) {
            s = __ldg(&g_csr[j]);
            float4 asv = *(const float4*)&g_as1[s * 4];
            p.x = __expf(lrelu(asv.x + adv.x));
            p.y = __expf(lrelu(asv.y + adv.y));
            p.z = __expf(lrelu(asv.z + adv.z));
            p.w = __expf(lrelu(asv.w + adv.w));
            z0 += p.x; z1 += p.y; z2 += p.z; z3 += p.w;
        }
        __syncwarp();
        sm_src[wslot][lane] = s;
        *(float4*)&sm_p[wslot][lane][0] = p;
        __syncwarp();
        int cnt = min(32, s1 - base);
        #pragma unroll 4
        for (int jj = 0; jj < cnt; jj++) {
            int   ss = sm_src[wslot][jj];
            float q  = sm_p[wslot][jj][head];
            uint2 u = *(const uint2*)&h[ss * 128 + (lane << 2)];
            float2 f01 = __half22float2(*reinterpret_cast<__half2*>(&u.x));
            float2 f23 = __half22float2(*reinterpret_cast<__half2*>(&u.y));
            acc.x += q * f01.x; acc.y += q * f01.y;
            acc.z += q * f23.x; acc.w += q * f23.y;
        }
    }
    #pragma unroll
    for (int off = 16; off; off >>= 1) {
        z0 += __shfl_xor_sync(FULL, z0, off);
        z1 += __shfl_xor_sync(FULL, z1, off);
        z2 += __shfl_xor_sync(FULL, z2, off);
        z3 += __shfl_xor_sync(FULL, z3, off);
    }
    float z = head == 0 ? z0 : head == 1 ? z1 : head == 2 ? z2 : z3;
    float inv = 1.f / z;
    int c = lane * 4;
    float4 bv = *(const float4*)&b[c];
    __half2 v01 = __floats2half2_rn(elu(acc.x * inv + bv.x), elu(acc.y * inv + bv.y));
    __half2 v23 = __floats2half2_rn(elu(acc.z * inv + bv.z), elu(acc.w * inv + bv.w));
    uint2 st;
    st.x = *reinterpret_cast<unsigned*>(&v01);
    st.y = *reinterpret_cast<unsigned*>(&v23);
    *(uint2*)&out[node * 128 + c] = st;
}

// ---------------- GAT aggregation, layer 2 (1 head), fp16 gather ----------------
__global__ void att2_k(const __half* __restrict__ h, const float* __restrict__ b,
                       float* __restrict__ out, int n) {
    __shared__ float2 sm2[8][32];
    int node = (blockIdx.x * blockDim.x + threadIdx.x) >> 5;
    int lane = threadIdx.x & 31;
    int wslot = (threadIdx.x >> 5) & 7;
    if (node >= n) return;
    int s0 = g_rowptr[node], s1 = g_rowptr[node + 1];

    float ad = g_ad2[node];
    float4 acc = make_float4(0.f, 0.f, 0.f, 0.f);
    float z = 0.f;
    for (int base = s0; base < s1; base += 32) {
        int j = base + lane;
        int s = 0; float p = 0.f;
        if (j < s1) {
            s = __ldg(&g_csr[j]);
            p = __expf(lrelu(g_as2[s] + ad));
            z += p;
        }
        __syncwarp();
        sm2[wslot][lane] = make_float2(__int_as_float(s), p);
        __syncwarp();
        int cnt = min(32, s1 - base);
        #pragma unroll 4
        for (int jj = 0; jj < cnt; jj++) {
            float2 sp = sm2[wslot][jj];
            int   ss = __float_as_int(sp.x);
            float q  = sp.y;
            uint2 u = *(const uint2*)&h[ss * 128 + (lane << 2)];
            float2 f01 = __half22float2(*reinterpret_cast<__half2*>(&u.x));
            float2 f23 = __half22float2(*reinterpret_cast<__half2*>(&u.y));
            acc.x += q * f01.x; acc.y += q * f01.y;
            acc.z += q * f23.x; acc.w += q * f23.y;
        }
    }
    #pragma unroll
    for (int off = 16; off; off >>= 1)
        z += __shfl_xor_sync(FULL, z, off);
    float inv = 1.f / z;
    int c = lane * 4;
    float4 bv = *(const float4*)&b[c];
    float4 o;
    o.x = elu(acc.x * inv + bv.x);
    o.y = elu(acc.y * inv + bv.y);
    o.z = elu(acc.z * inv + bv.z);
    o.w = elu(acc.w * inv + bv.w);
    *(float4*)&out[node * 128 + c] = o;
}

// ---------------- final linear head: [n,128] @ [128,40] + b ----------------
__global__ void head_k(const float* __restrict__ A, const float* __restrict__ W,
                       const float* __restrict__ b, float* __restrict__ out, int n) {
    int i = blockIdx.x * blockDim.x + threadIdx.x;
    if (i >= n * 40) return;
    int row = i / 40, c = i - row * 40;
    const float* xr = &A[row * 128];
    float acc = b[c];
    #pragma unroll 8
    for (int k = 0; k < 128; k++)
        acc += xr[k] * __ldg(&W[k * 40 + c]);
    out[i] = acc;
}

// ---------------- launch ----------------
extern "C" void kernel_launch(void* const* d_in, const int* in_sizes, int n_in,
                              void* d_out, int out_size) {
    const float* x   = (const float*)d_in[0];
    const int*   ei  = (const int*)  d_in[1];
    const float* W1  = (const float*)d_in[2];
    const float* as1 = (const float*)d_in[3];
    const float* ad1 = (const float*)d_in[4];
    const float* b1  = (const float*)d_in[5];
    const float* W2  = (const float*)d_in[6];
    const float* as2 = (const float*)d_in[7];
    const float* ad2 = (const float*)d_in[8];
    const float* b2  = (const float*)d_in[9];
    const float* Wl  = (const float*)d_in[10];
    const float* bl  = (const float*)d_in[11];
    float* out = (float*)d_out;

    const int n = in_sizes[0] / 128;   // 10000
    const int e = in_sizes[1] / 2;     // 640000

    __half *B1t, *B2t, *h1h, *h2h, *o1h;
    float *o2, *pas1, *pad1, *pas2, *pad2;
    cudaGetSymbolAddress((void**)&B1t, g_B1t);
    cudaGetSymbolAddress((void**)&B2t, g_B2t);
    cudaGetSymbolAddress((void**)&h1h, g_h1h);
    cudaGetSymbolAddress((void**)&h2h, g_h2h);
    cudaGetSymbolAddress((void**)&o1h, g_o1h);
    cudaGetSymbolAddress((void**)&o2,  g_o2);
    cudaGetSymbolAddress((void**)&pas1, g_as1);
    cudaGetSymbolAddress((void**)&pad1, g_ad1);
    cudaGetSymbolAddress((void**)&pas2, g_as2);
    cudaGetSymbolAddress((void**)&pad2, g_ad2);

    int q = e >> 2, tail = e & 3;
    int ethreads = q + tail;

    // CSR build (one atomic pass; rank-based fill, no second atomic round)
    hist_k<<<(ethreads + 255) / 256, 256>>>(ei, e);
    scan_k<<<1, 1024>>>(n);
    fill_k<<<(ethreads + 255) / 256, 256>>>(ei, e);

    // weight conversion (fp16, transposed k-contiguous)
    wcvt_k<<<64, 256>>>(W1, B1t);
    wcvt_k<<<64, 256>>>(W2, B2t);

    // layer 1
    gemm16_k<4, true><<<(n + 15) / 16, 128>>>(x, B1t, as1, ad1, h1h, pas1, pad1, n);
    att1_k<<<(n * 32 + 255) / 256, 256>>>(h1h, b1, o1h, n);

    // layer 2
    gemm16_k<1, false><<<(n + 15) / 16, 128>>>(o1h, B2t, as2, ad2, h2h, pas2, pad2, n);
    att2_k<<<(n * 32 + 255) / 256, 256>>>(h2h, b2, o2, n);

    // head
    head_k<<<(n * 40 + 255) / 256, 256>>>(o2, Wl, bl, out, n);
}

// round 9
// speedup vs baseline: 1.4225x; 1.0021x over previous
#include <cuda_runtime.h>
#include <cuda_fp16.h>
#include <math.h>

#define NN   10000
#define EE   640000
#define TOTE (EE + NN)
#define FULL 0xFFFFFFFFu

// ---------------- scratch (static device globals; no allocation) ----------------
__device__ int   g_deg[NN];          // zero-initialized at load; scan_k re-zeroes after use
__device__ int   g_rowptr[NN + 1];
__device__ int   g_rank[EE];         // per-edge rank within its dst row
__device__ int   g_csr[TOTE];

__device__ __half g_B1t[128 * 128];  // fp16 W1, transposed: Bt[c*128+k] = W[k*128+c]
__device__ __half g_B2t[128 * 128];  // fp16 W2, transposed
__device__ __half g_h1h[NN * 128];   // fp16 h1 = x @ W1 (gather table)
__device__ __half g_o1h[NN * 128];   // fp16 elu(gat1) -> input of gemm2
__device__ __half g_h2h[NN * 128];   // fp16 h2 = o1 @ W2 (gather table)
__device__ float  g_o2[NN * 128];    // fp32 elu(gat2) -> input of head

__device__ float g_as1[NN * 4];
__device__ float g_ad1[NN * 4];
__device__ float g_as2[NN];
__device__ float g_ad2[NN];

__device__ __forceinline__ float lrelu(float v) { return v > 0.f ? v : 0.2f * v; }
__device__ __forceinline__ float elu(float v)   { return v > 0.f ? v : (expf(v) - 1.f); }

// ---------------- fused kernel 1: edge histogram (+rank) | weight convert ----------------
// blocks [0, HB): hist — one atomic pass, rank = atomicAdd return value.
// blocks [HB, ...): convert both W1, W2 to fp16 transposed (k-contiguous).
__global__ void combo1_k(const int* __restrict__ ei, int e,
                         const float* __restrict__ W1, const float* __restrict__ W2,
                         __half* __restrict__ B1t, __half* __restrict__ B2t, int HB) {
    int t = threadIdx.x;
    if ((int)blockIdx.x < HB) {
        int i = blockIdx.x * 256 + t;
        int q = e >> 2;
        if (i < q) {
            int4 d = ((const int4*)(ei + e))[i];
            int4 r;
            r.x = atomicAdd(&g_deg[d.x], 1);
            r.y = atomicAdd(&g_deg[d.y], 1);
            r.z = atomicAdd(&g_deg[d.z], 1);
            r.w = atomicAdd(&g_deg[d.w], 1);
            ((int4*)g_rank)[i] = r;
        } else {
            int r = (q << 2) + (i - q);         // scalar tail (e % 4 edges)
            if (r < e) g_rank[r] = atomicAdd(&g_deg[ei[e + r]], 1);
        }
    } else {
        // 32768 total fp16 outputs, 4 per thread (one 8B store each)
        int tid = (blockIdx.x - HB) * 256 + t;
        int base = tid * 4;
        if (base < 2 * 128 * 128) {
            const float* W = (base < 128 * 128) ? W1 : W2;
            __half* Bt     = (base < 128 * 128) ? B1t : B2t;
            int off = base & (128 * 128 - 1);
            int c = off >> 7, k = off & 127;    // k multiple of 4, stays in row
            float v0 = W[(k + 0) * 128 + c];
            float v1 = W[(k + 1) * 128 + c];
            float v2 = W[(k + 2) * 128 + c];
            float v3 = W[(k + 3) * 128 + c];
            __half2 h01 = __floats2half2_rn(v0, v1);
            __half2 h23 = __floats2half2_rn(v2, v3);
            uint2 st;
            st.x = *reinterpret_cast<unsigned*>(&h01);
            st.y = *reinterpret_cast<unsigned*>(&h23);
            *(uint2*)&Bt[c * 128 + k] = st;
        }
    }
}

// single-pass block scan over deg+1 (self loop); writes rowptr, self-loop CSR slot,
// and re-zeroes g_deg for the next launch (keeps kernel_launch deterministic).
__global__ void scan_k(int n) {
    __shared__ int wsum[32];
    int t = threadIdx.x, lane = t & 31, wid = t >> 5;
    int items = (n + 1023) >> 10;               // 10 for n=10000
    int base = t * items;
    int v[16];
    int sum = 0;
    #pragma unroll
    for (int i = 0; i < 16; i++) {
        if (i >= items) break;
        int idx = base + i;
        int x = 0;
        if (idx < n) { x = g_deg[idx] + 1; g_deg[idx] = 0; }
        v[i] = sum;                             // thread-local exclusive prefix
        sum += x;
    }
    int incl = sum;
    #pragma unroll
    for (int off = 1; off < 32; off <<= 1) {
        int y = __shfl_up_sync(FULL, incl, off);
        if (lane >= off) incl += y;
    }
    if (lane == 31) wsum[wid] = incl;
    __syncthreads();
    if (wid == 0) {
        int wv = wsum[lane];
        int wi = wv;
        #pragma unroll
        for (int off = 1; off < 32; off <<= 1) {
            int y = __shfl_up_sync(FULL, wi, off);
            if (lane >= off) wi += y;
        }
        wsum[lane] = wi - wv;                   // exclusive warp offsets
    }
    __syncthreads();
    int off = wsum[wid] + incl - sum;           // exclusive offset for this thread
    #pragma unroll
    for (int i = 0; i < 16; i++) {
        if (i >= items) break;
        int idx = base + i;
        if (idx < n) {
            int p = off + v[i];
            g_rowptr[idx] = p;
            g_csr[p] = idx;                     // self loop occupies slot 0
        }
    }
    if (t == 1023) g_rowptr[n] = off + sum;     // grand total
}

// ---- tensor-core GEMM + fused attention-scalar epilogue (device body) ----
// 128 threads (4 warps), tile 16 rows x 128 cols; warp w owns cols [32w,32w+32).
// mma.m16n8k16 fp16 in / fp32 accum. AFP32: stage-convert A; else A already fp16.
template<int HEADS, bool AFP32>
__device__ __forceinline__ void gemm16_body(
        int blk, const void* __restrict__ Avoid, const __half* __restrict__ Bt,
        const float* __restrict__ a_src, const float* __restrict__ a_dst,
        __half* __restrict__ H16,
        float* __restrict__ as_out, float* __restrict__ ad_out, int n) {
    __shared__ __align__(16) __half As[16][136];   // pad 8 halves: conflict-free frag loads
    __shared__ __align__(16) float  xs[16][128];   // fp32 result staging for a·h epilogue
    int row0 = blk * 16;
    int t = threadIdx.x, lane = t & 31, w = t >> 5;

    // stage A (16 rows) as fp16
    for (int i = t; i < 16 * 32; i += 128) {
        int r = i >> 5, k4 = (i & 31) << 2;
        int row = row0 + r;
        if (AFP32) {
            const float* Af = (const float*)Avoid;
            float4 v = (row < n) ? *(const float4*)&Af[row * 128 + k4]
                                 : make_float4(0.f, 0.f, 0.f, 0.f);
            *(__half2*)&As[r][k4]     = __floats2half2_rn(v.x, v.y);
            *(__half2*)&As[r][k4 + 2] = __floats2half2_rn(v.z, v.w);
        } else {
            const __half* Ah = (const __half*)Avoid;
            uint2 v = (row < n) ? *(const uint2*)&Ah[row * 128 + k4] : make_uint2(0u, 0u);
            *(uint2*)&As[r][k4] = v;
        }
    }
    __syncthreads();

    int g = lane >> 2, t4 = lane & 3;
    float c[4][4];
    #pragma unroll
    for (int nt = 0; nt < 4; nt++)
        #pragma unroll
        for (int i = 0; i < 4; i++) c[nt][i] = 0.f;

    #pragma unroll
    for (int kc = 0; kc < 128; kc += 16) {
        unsigned a0 = *(const unsigned*)&As[g][kc + t4 * 2];
        unsigned a1 = *(const unsigned*)&As[g + 8][kc + t4 * 2];
        unsigned a2 = *(const unsigned*)&As[g][kc + 8 + t4 * 2];
        unsigned a3 = *(const unsigned*)&As[g + 8][kc + 8 + t4 * 2];
        #pragma unroll
        for (int nt = 0; nt < 4; nt++) {
            int col = (w * 4 + nt) * 8 + g;            // B-frag col = groupID
            unsigned b0 = *(const unsigned*)&Bt[col * 128 + kc + t4 * 2];
            unsigned b1 = *(const unsigned*)&Bt[col * 128 + kc + 8 + t4 * 2];
            asm volatile(
                "mma.sync.aligned.m16n8k16.row.col.f32.f16.f16.f32 "
                "{%0,%1,%2,%3}, {%4,%5,%6,%7}, {%8,%9}, {%0,%1,%2,%3};"
                : "+f"(c[nt][0]), "+f"(c[nt][1]), "+f"(c[nt][2]), "+f"(c[nt][3])
                : "r"(a0), "r"(a1), "r"(a2), "r"(a3), "r"(b0), "r"(b1));
        }
    }

    __syncthreads();   // before reusing xs
    #pragma unroll
    for (int nt = 0; nt < 4; nt++) {
        int colb = (w * 4 + nt) * 8 + t4 * 2;          // C-frag col = t4*2
        int r0 = row0 + g, r1 = row0 + g + 8;
        if (r0 < n) {
            *(__half2*)&H16[r0 * 128 + colb] = __floats2half2_rn(c[nt][0], c[nt][1]);
            xs[g][colb]     = c[nt][0];
            xs[g][colb + 1] = c[nt][1];
        }
        if (r1 < n) {
            *(__half2*)&H16[r1 * 128 + colb] = __floats2half2_rn(c[nt][2], c[nt][3]);
            xs[g + 8][colb]     = c[nt][2];
            xs[g + 8][colb + 1] = c[nt][3];
        }
    }
    __syncthreads();

    // a·h epilogue: 4 warps x 4 rows
    float4 sv = *(const float4*)&a_src[lane * 4];
    float4 dv = *(const float4*)&a_dst[lane * 4];
    #pragma unroll
    for (int r4 = 0; r4 < 4; r4++) {
        int r = w * 4 + r4;
        float4 hv = *(const float4*)&xs[r][lane * 4];
        float ps = hv.x * sv.x + hv.y * sv.y + hv.z * sv.z + hv.w * sv.w;
        float pd = hv.x * dv.x + hv.y * dv.y + hv.z * dv.z + hv.w * dv.w;
        if (HEADS == 4) {
            #pragma unroll
            for (int off = 1; off < 8; off <<= 1) {
                ps += __shfl_xor_sync(FULL, ps, off);
                pd += __shfl_xor_sync(FULL, pd, off);
            }
            int row = row0 + r;
            if (row < n && (lane & 7) == 0) {
                as_out[row * 4 + (lane >> 3)] = ps;
                ad_out[row * 4 + (lane >> 3)] = pd;
            }
        } else {
            #pragma unroll
            for (int off = 1; off < 32; off <<= 1) {
                ps += __shfl_xor_sync(FULL, ps, off);
                pd += __shfl_xor_sync(FULL, pd, off);
            }
            int row = row0 + r;
            if (row < n && lane == 0) { as_out[row] = ps; ad_out[row] = pd; }
        }
    }
}

// ---------------- fused kernel 2: CSR fill | layer-1 GEMM (independent stages) ----------------
// blocks [0, FB): fill (no atomics; position = rowptr[dst] + 1 + rank), 128 threads.
// blocks [FB, ...): gemm16<4, fp32-A> on x/W1.
__global__ void combo2_k(const int* __restrict__ ei, int e,
                         const float* __restrict__ x, const __half* __restrict__ B1t,
                         const float* __restrict__ a_src, const float* __restrict__ a_dst,
                         __half* __restrict__ H16,
                         float* __restrict__ as_out, float* __restrict__ ad_out,
                         int n, int FB) {
    if ((int)blockIdx.x < FB) {
        int i = blockIdx.x * 128 + threadIdx.x;
        int q = e >> 2;
        if (i < q) {
            int4 s = ((const int4*)ei)[i];
            int4 d = ((const int4*)(ei + e))[i];
            int4 r = ((const int4*)g_rank)[i];
            g_csr[g_rowptr[d.x] + 1 + r.x] = s.x;
            g_csr[g_rowptr[d.y] + 1 + r.y] = s.y;
            g_csr[g_rowptr[d.z] + 1 + r.z] = s.z;
            g_csr[g_rowptr[d.w] + 1 + r.w] = s.w;
        } else {
            int r = i - q;
            int tail = e & 3;
            if (r < tail) {                     // scalar tail edges
                int idx = (q << 2) + r;
                g_csr[g_rowptr[ei[e + idx]] + 1 + g_rank[idx]] = ei[idx];
            }
            // (self loops already written by scan_k)
        }
    } else {
        gemm16_body<4, true>(blockIdx.x - FB, x, B1t, a_src, a_dst,
                             H16, as_out, ad_out, n);
    }
}

// standalone layer-2 GEMM (A fp16)
__global__ void gemm2_k(const __half* __restrict__ A, const __half* __restrict__ Bt,
                        const float* __restrict__ a_src, const float* __restrict__ a_dst,
                        __half* __restrict__ H16,
                        float* __restrict__ as_out, float* __restrict__ ad_out, int n) {
    gemm16_body<1, false>(blockIdx.x, A, Bt, a_src, a_dst, H16, as_out, ad_out, n);
}

// ---------------- GAT aggregation, layer 1 (4 heads), fp16 gather, fp16 out ----------------
__global__ void att1_k(const __half* __restrict__ h, const float* __restrict__ b,
                       __half* __restrict__ out, int n) {
    __shared__ int   sm_src[8][32];
    __shared__ float sm_p[8][32][4];
    int node = (blockIdx.x * blockDim.x + threadIdx.x) >> 5;
    int lane = threadIdx.x & 31;
    int wslot = (threadIdx.x >> 5) & 7;
    if (node >= n) return;
    int s0 = g_rowptr[node], s1 = g_rowptr[node + 1];

    float4 adv = *(const float4*)&g_ad1[node * 4];
    int head = lane >> 3;
    float4 acc = make_float4(0.f, 0.f, 0.f, 0.f);
    float z0 = 0.f, z1 = 0.f, z2 = 0.f, z3 = 0.f;

    for (int base = s0; base < s1; base += 32) {
        int j = base + lane;
        int s = 0;
        float4 p = make_float4(0.f, 0.f, 0.f, 0.f);
        if (j < s1) {
            s = __ldg(&g_csr[j]);
            float4 asv = *(const float4*)&g_as1[s * 4];
            p.x = __expf(lrelu(asv.x + adv.x));
            p.y = __expf(lrelu(asv.y + adv.y));
            p.z = __expf(lrelu(asv.z + adv.z));
            p.w = __expf(lrelu(asv.w + adv.w));
            z0 += p.x; z1 += p.y; z2 += p.z; z3 += p.w;
        }
        __syncwarp();
        sm_src[wslot][lane] = s;
        *(float4*)&sm_p[wslot][lane][0] = p;
        __syncwarp();
        int cnt = min(32, s1 - base);
        #pragma unroll 4
        for (int jj = 0; jj < cnt; jj++) {
            int   ss = sm_src[wslot][jj];
            float q  = sm_p[wslot][jj][head];
            uint2 u = *(const uint2*)&h[ss * 128 + (lane << 2)];
            float2 f01 = __half22float2(*reinterpret_cast<__half2*>(&u.x));
            float2 f23 = __half22float2(*reinterpret_cast<__half2*>(&u.y));
            acc.x += q * f01.x; acc.y += q * f01.y;
            acc.z += q * f23.x; acc.w += q * f23.y;
        }
    }
    #pragma unroll
    for (int off = 16; off; off >>= 1) {
        z0 += __shfl_xor_sync(FULL, z0, off);
        z1 += __shfl_xor_sync(FULL, z1, off);
        z2 += __shfl_xor_sync(FULL, z2, off);
        z3 += __shfl_xor_sync(FULL, z3, off);
    }
    float z = head == 0 ? z0 : head == 1 ? z1 : head == 2 ? z2 : z3;
    float inv = 1.f / z;
    int c = lane * 4;
    float4 bv = *(const float4*)&b[c];
    __half2 v01 = __floats2half2_rn(elu(acc.x * inv + bv.x), elu(acc.y * inv + bv.y));
    __half2 v23 = __floats2half2_rn(elu(acc.z * inv + bv.z), elu(acc.w * inv + bv.w));
    uint2 st;
    st.x = *reinterpret_cast<unsigned*>(&v01);
    st.y = *reinterpret_cast<unsigned*>(&v23);
    *(uint2*)&out[node * 128 + c] = st;
}

// ---------------- GAT aggregation, layer 2 (1 head), fp16 gather ----------------
__global__ void att2_k(const __half* __restrict__ h, const float* __restrict__ b,
                       float* __restrict__ out, int n) {
    __shared__ float2 sm2[8][32];
    int node = (blockIdx.x * blockDim.x + threadIdx.x) >> 5;
    int lane = threadIdx.x & 31;
    int wslot = (threadIdx.x >> 5) & 7;
    if (node >= n) return;
    int s0 = g_rowptr[node], s1 = g_rowptr[node + 1];

    float ad = g_ad2[node];
    float4 acc = make_float4(0.f, 0.f, 0.f, 0.f);
    float z = 0.f;
    for (int base = s0; base < s1; base += 32) {
        int j = base + lane;
        int s = 0; float p = 0.f;
        if (j < s1) {
            s = __ldg(&g_csr[j]);
            p = __expf(lrelu(g_as2[s] + ad));
            z += p;
        }
        __syncwarp();
        sm2[wslot][lane] = make_float2(__int_as_float(s), p);
        __syncwarp();
        int cnt = min(32, s1 - base);
        #pragma unroll 4
        for (int jj = 0; jj < cnt; jj++) {
            float2 sp = sm2[wslot][jj];
            int   ss = __float_as_int(sp.x);
            float q  = sp.y;
            uint2 u = *(const uint2*)&h[ss * 128 + (lane << 2)];
            float2 f01 = __half22float2(*reinterpret_cast<__half2*>(&u.x));
            float2 f23 = __half22float2(*reinterpret_cast<__half2*>(&u.y));
            acc.x += q * f01.x; acc.y += q * f01.y;
            acc.z += q * f23.x; acc.w += q * f23.y;
        }
    }
    #pragma unroll
    for (int off = 16; off; off >>= 1)
        z += __shfl_xor_sync(FULL, z, off);
    float inv = 1.f / z;
    int c = lane * 4;
    float4 bv = *(const float4*)&b[c];
    float4 o;
    o.x = elu(acc.x * inv + bv.x);
    o.y = elu(acc.y * inv + bv.y);
    o.z = elu(acc.z * inv + bv.z);
    o.w = elu(acc.w * inv + bv.w);
    *(float4*)&out[node * 128 + c] = o;
}

// ---------------- final linear head: [n,128] @ [128,40] + b ----------------
__global__ void head_k(const float* __restrict__ A, const float* __restrict__ W,
                       const float* __restrict__ b, float* __restrict__ out, int n) {
    int i = blockIdx.x * blockDim.x + threadIdx.x;
    if (i >= n * 40) return;
    int row = i / 40, c = i - row * 40;
    const float* xr = &A[row * 128];
    float acc = b[c];
    #pragma unroll 8
    for (int k = 0; k < 128; k++)
        acc += xr[k] * __ldg(&W[k * 40 + c]);
    out[i] = acc;
}

// ---------------- launch ----------------
extern "C" void kernel_launch(void* const* d_in, const int* in_sizes, int n_in,
                              void* d_out, int out_size) {
    const float* x   = (const float*)d_in[0];
    const int*   ei  = (const int*)  d_in[1];
    const float* W1  = (const float*)d_in[2];
    const float* as1 = (const float*)d_in[3];
    const float* ad1 = (const float*)d_in[4];
    const float* b1  = (const float*)d_in[5];
    const float* W2  = (const float*)d_in[6];
    const float* as2 = (const float*)d_in[7];
    const float* ad2 = (const float*)d_in[8];
    const float* b2  = (const float*)d_in[9];
    const float* Wl  = (const float*)d_in[10];
    const float* bl  = (const float*)d_in[11];
    float* out = (float*)d_out;

    const int n = in_sizes[0] / 128;   // 10000
    const int e = in_sizes[1] / 2;     // 640000

    __half *B1t, *B2t, *h1h, *h2h, *o1h;
    float *o2, *pas1, *pad1, *pas2, *pad2;
    cudaGetSymbolAddress((void**)&B1t, g_B1t);
    cudaGetSymbolAddress((void**)&B2t, g_B2t);
    cudaGetSymbolAddress((void**)&h1h, g_h1h);
    cudaGetSymbolAddress((void**)&h2h, g_h2h);
    cudaGetSymbolAddress((void**)&o1h, g_o1h);
    cudaGetSymbolAddress((void**)&o2,  g_o2);
    cudaGetSymbolAddress((void**)&pas1, g_as1);
    cudaGetSymbolAddress((void**)&pad1, g_ad1);
    cudaGetSymbolAddress((void**)&pas2, g_as2);
    cudaGetSymbolAddress((void**)&pad2, g_ad2);

    int q = e >> 2, tail = e & 3;

    // K1: hist + weight convert (independent; co-scheduled)
    int HB = (q + tail + 255) / 256;
    int WB = (2 * 128 * 128 / 4 + 255) / 256;   // 32 blocks
    combo1_k<<<HB + WB, 256>>>(ei, e, W1, W2, B1t, B2t, HB);

    // K2: scan (rowptr + self-loop slots + deg reset)
    scan_k<<<1, 1024>>>(n);

    // K3: fill + layer-1 GEMM (independent; co-scheduled)
    int FB = (q + tail + 127) / 128;
    int GB = (n + 15) / 16;
    combo2_k<<<FB + GB, 128>>>(ei, e, x, B1t, as1, ad1, h1h, pas1, pad1, n, FB);

    // K4: layer-1 aggregation
    att1_k<<<(n * 32 + 255) / 256, 256>>>(h1h, b1, o1h, n);

    // K5: layer-2 GEMM
    gemm2_k<<<(n + 15) / 16, 128>>>(o1h, B2t, as2, ad2, h2h, pas2, pad2, n);

    // K6: layer-2 aggregation
    att2_k<<<(n * 32 + 255) / 256, 256>>>(h2h, b2, o2, n);

    // K7: head
    head_k<<<(n * 40 + 255) / 256, 256>>>(o2, Wl, bl, out, n);
}

// round 11
// speedup vs baseline: 1.4500x; 1.0194x over previous
#include <cuda_runtime.h>
#include <cuda_fp16.h>
#include <math.h>

#define NN   10000
#define EE   640000
#define TOTE (EE + NN)
#define FULL 0xFFFFFFFFu

// ---------------- scratch (static device globals; no allocation) ----------------
__device__ int   g_deg[NN];          // zero-initialized at load; scan_k re-zeroes after use
__device__ int   g_rowptr[NN + 1];
__device__ int   g_rank[EE];         // per-edge rank within its dst row
__device__ int   g_csr[TOTE];

__device__ __half g_B1t[128 * 128];  // fp16 W1, transposed: Bt[c*128+k] = W[k*128+c]
__device__ __half g_B2t[128 * 128];  // fp16 W2, transposed
__device__ __half g_h1h[NN * 128];   // fp16 h1 = x @ W1 (gather table)
__device__ __half g_o1h[NN * 128];   // fp16 elu(gat1) -> input of gemm2
__device__ __half g_h2h[NN * 128];   // fp16 h2 = o1 @ W2 (gather table)
__device__ float  g_o2[NN * 128];    // fp32 elu(gat2) -> input of head

__device__ float g_as1[NN * 4];
__device__ float g_ad1[NN * 4];
__device__ float g_as2[NN];
__device__ float g_ad2[NN];

__device__ __forceinline__ float lrelu(float v) { return v > 0.f ? v : 0.2f * v; }
__device__ __forceinline__ float elu(float v)   { return v > 0.f ? v : (expf(v) - 1.f); }

// ---------------- fused kernel 1: edge histogram (+rank) | weight convert ----------------
__global__ void combo1_k(const int* __restrict__ ei, int e,
                         const float* __restrict__ W1, const float* __restrict__ W2,
                         __half* __restrict__ B1t, __half* __restrict__ B2t, int HB) {
    int t = threadIdx.x;
    if ((int)blockIdx.x < HB) {
        int i = blockIdx.x * 256 + t;
        int q = e >> 2;
        if (i < q) {
            int4 d = ((const int4*)(ei + e))[i];
            int4 r;
            r.x = atomicAdd(&g_deg[d.x], 1);
            r.y = atomicAdd(&g_deg[d.y], 1);
            r.z = atomicAdd(&g_deg[d.z], 1);
            r.w = atomicAdd(&g_deg[d.w], 1);
            ((int4*)g_rank)[i] = r;
        } else {
            int r = (q << 2) + (i - q);         // scalar tail (e % 4 edges)
            if (r < e) g_rank[r] = atomicAdd(&g_deg[ei[e + r]], 1);
        }
    } else {
        int tid = (blockIdx.x - HB) * 256 + t;
        int base = tid * 4;
        if (base < 2 * 128 * 128) {
            const float* W = (base < 128 * 128) ? W1 : W2;
            __half* Bt     = (base < 128 * 128) ? B1t : B2t;
            int off = base & (128 * 128 - 1);
            int c = off >> 7, k = off & 127;
            float v0 = W[(k + 0) * 128 + c];
            float v1 = W[(k + 1) * 128 + c];
            float v2 = W[(k + 2) * 128 + c];
            float v3 = W[(k + 3) * 128 + c];
            __half2 h01 = __floats2half2_rn(v0, v1);
            __half2 h23 = __floats2half2_rn(v2, v3);
            uint2 st;
            st.x = *reinterpret_cast<unsigned*>(&h01);
            st.y = *reinterpret_cast<unsigned*>(&h23);
            *(uint2*)&Bt[c * 128 + k] = st;
        }
    }
}

// single-pass block scan over deg+1 (self loop); writes rowptr, self-loop CSR slot,
// and re-zeroes g_deg for the next launch.
__global__ void scan_k(int n) {
    __shared__ int wsum[32];
    int t = threadIdx.x, lane = t & 31, wid = t >> 5;
    int items = (n + 1023) >> 10;
    int base = t * items;
    int v[16];
    int sum = 0;
    #pragma unroll
    for (int i = 0; i < 16; i++) {
        if (i >= items) break;
        int idx = base + i;
        int x = 0;
        if (idx < n) { x = g_deg[idx] + 1; g_deg[idx] = 0; }
        v[i] = sum;
        sum += x;
    }
    int incl = sum;
    #pragma unroll
    for (int off = 1; off < 32; off <<= 1) {
        int y = __shfl_up_sync(FULL, incl, off);
        if (lane >= off) incl += y;
    }
    if (lane == 31) wsum[wid] = incl;
    __syncthreads();
    if (wid == 0) {
        int wv = wsum[lane];
        int wi = wv;
        #pragma unroll
        for (int off = 1; off < 32; off <<= 1) {
            int y = __shfl_up_sync(FULL, wi, off);
            if (lane >= off) wi += y;
        }
        wsum[lane] = wi - wv;
    }
    __syncthreads();
    int off = wsum[wid] + incl - sum;
    #pragma unroll
    for (int i = 0; i < 16; i++) {
        if (i >= items) break;
        int idx = base + i;
        if (idx < n) {
            int p = off + v[i];
            g_rowptr[idx] = p;
            g_csr[p] = idx;                     // self loop occupies slot 0
        }
    }
    if (t == 1023) g_rowptr[n] = off + sum;
}

// ---- tensor-core GEMM + fused attention-scalar epilogue (device body) ----
template<int HEADS, bool AFP32>
__device__ __forceinline__ void gemm16_body(
        int blk, const void* __restrict__ Avoid, const __half* __restrict__ Bt,
        const float* __restrict__ a_src, const float* __restrict__ a_dst,
        __half* __restrict__ H16,
        float* __restrict__ as_out, float* __restrict__ ad_out, int n) {
    __shared__ __align__(16) __half As[16][136];
    __shared__ __align__(16) float  xs[16][128];
    int row0 = blk * 16;
    int t = threadIdx.x, lane = t & 31, w = t >> 5;

    for (int i = t; i < 16 * 32; i += 128) {
        int r = i >> 5, k4 = (i & 31) << 2;
        int row = row0 + r;
        if (AFP32) {
            const float* Af = (const float*)Avoid;
            float4 v = (row < n) ? *(const float4*)&Af[row * 128 + k4]
                                 : make_float4(0.f, 0.f, 0.f, 0.f);
            *(__half2*)&As[r][k4]     = __floats2half2_rn(v.x, v.y);
            *(__half2*)&As[r][k4 + 2] = __floats2half2_rn(v.z, v.w);
        } else {
            const __half* Ah = (const __half*)Avoid;
            uint2 v = (row < n) ? *(const uint2*)&Ah[row * 128 + k4] : make_uint2(0u, 0u);
            *(uint2*)&As[r][k4] = v;
        }
    }
    __syncthreads();

    int g = lane >> 2, t4 = lane & 3;
    float c[4][4];
    #pragma unroll
    for (int nt = 0; nt < 4; nt++)
        #pragma unroll
        for (int i = 0; i < 4; i++) c[nt][i] = 0.f;

    #pragma unroll
    for (int kc = 0; kc < 128; kc += 16) {
        unsigned a0 = *(const unsigned*)&As[g][kc + t4 * 2];
        unsigned a1 = *(const unsigned*)&As[g + 8][kc + t4 * 2];
        unsigned a2 = *(const unsigned*)&As[g][kc + 8 + t4 * 2];
        unsigned a3 = *(const unsigned*)&As[g + 8][kc + 8 + t4 * 2];
        #pragma unroll
        for (int nt = 0; nt < 4; nt++) {
            int col = (w * 4 + nt) * 8 + g;
            unsigned b0 = *(const unsigned*)&Bt[col * 128 + kc + t4 * 2];
            unsigned b1 = *(const unsigned*)&Bt[col * 128 + kc + 8 + t4 * 2];
            asm volatile(
                "mma.sync.aligned.m16n8k16.row.col.f32.f16.f16.f32 "
                "{%0,%1,%2,%3}, {%4,%5,%6,%7}, {%8,%9}, {%0,%1,%2,%3};"
                : "+f"(c[nt][0]), "+f"(c[nt][1]), "+f"(c[nt][2]), "+f"(c[nt][3])
                : "r"(a0), "r"(a1), "r"(a2), "r"(a3), "r"(b0), "r"(b1));
        }
    }

    __syncthreads();
    #pragma unroll
    for (int nt = 0; nt < 4; nt++) {
        int colb = (w * 4 + nt) * 8 + t4 * 2;
        int r0 = row0 + g, r1 = row0 + g + 8;
        if (r0 < n) {
            *(__half2*)&H16[r0 * 128 + colb] = __floats2half2_rn(c[nt][0], c[nt][1]);
            xs[g][colb]     = c[nt][0];
            xs[g][colb + 1] = c[nt][1];
        }
        if (r1 < n) {
            *(__half2*)&H16[r1 * 128 + colb] = __floats2half2_rn(c[nt][2], c[nt][3]);
            xs[g + 8][colb]     = c[nt][2];
            xs[g + 8][colb + 1] = c[nt][3];
        }
    }
    __syncthreads();

    float4 sv = *(const float4*)&a_src[lane * 4];
    float4 dv = *(const float4*)&a_dst[lane * 4];
    #pragma unroll
    for (int r4 = 0; r4 < 4; r4++) {
        int r = w * 4 + r4;
        float4 hv = *(const float4*)&xs[r][lane * 4];
        float ps = hv.x * sv.x + hv.y * sv.y + hv.z * sv.z + hv.w * sv.w;
        float pd = hv.x * dv.x + hv.y * dv.y + hv.z * dv.z + hv.w * dv.w;
        if (HEADS == 4) {
            #pragma unroll
            for (int off = 1; off < 8; off <<= 1) {
                ps += __shfl_xor_sync(FULL, ps, off);
                pd += __shfl_xor_sync(FULL, pd, off);
            }
            int row = row0 + r;
            if (row < n && (lane & 7) == 0) {
                as_out[row * 4 + (lane >> 3)] = ps;
                ad_out[row * 4 + (lane >> 3)] = pd;
            }
        } else {
            #pragma unroll
            for (int off = 1; off < 32; off <<= 1) {
                ps += __shfl_xor_sync(FULL, ps, off);
                pd += __shfl_xor_sync(FULL, pd, off);
            }
            int row = row0 + r;
            if (row < n && lane == 0) { as_out[row] = ps; ad_out[row] = pd; }
        }
    }
}

// ---------------- fused kernel 2: CSR fill | layer-1 GEMM ----------------
__global__ void combo2_k(const int* __restrict__ ei, int e,
                         const float* __restrict__ x, const __half* __restrict__ B1t,
                         const float* __restrict__ a_src, const float* __restrict__ a_dst,
                         __half* __restrict__ H16,
                         float* __restrict__ as_out, float* __restrict__ ad_out,
                         int n, int FB) {
    if ((int)blockIdx.x < FB) {
        int i = blockIdx.x * 128 + threadIdx.x;
        int q = e >> 2;
        if (i < q) {
            int4 s = ((const int4*)ei)[i];
            int4 d = ((const int4*)(ei + e))[i];
            int4 r = ((const int4*)g_rank)[i];
            g_csr[g_rowptr[d.x] + 1 + r.x] = s.x;
            g_csr[g_rowptr[d.y] + 1 + r.y] = s.y;
            g_csr[g_rowptr[d.z] + 1 + r.z] = s.z;
            g_csr[g_rowptr[d.w] + 1 + r.w] = s.w;
        } else {
            int r = i - q;
            int tail = e & 3;
            if (r < tail) {
                int idx = (q << 2) + r;
                g_csr[g_rowptr[ei[e + idx]] + 1 + g_rank[idx]] = ei[idx];
            }
        }
    } else {
        gemm16_body<4, true>(blockIdx.x - FB, x, B1t, a_src, a_dst,
                             H16, as_out, ad_out, n);
    }
}

__global__ void gemm2_k(const __half* __restrict__ A, const __half* __restrict__ Bt,
                        const float* __restrict__ a_src, const float* __restrict__ a_dst,
                        __half* __restrict__ H16,
                        float* __restrict__ as_out, float* __restrict__ ad_out, int n) {
    gemm16_body<1, false>(blockIdx.x, A, Bt, a_src, a_dst, H16, as_out, ad_out, n);
}

// ---------------- GAT aggregation, layer 1 (4 heads) ----------------
// half-warp edge-pairing: lane owns 8 dims (hl = lane&15), half = lane>>4
// processes its own 16 staged edges; one LDG.128 gather + one LDS.64 (src,p) per edge.
__global__ void __launch_bounds__(256) att1_k(const __half* __restrict__ h,
                                              const float* __restrict__ b,
                                              __half* __restrict__ out, int n) {
    __shared__ float2 sm_hp[8][4][33];     // [warp][head][edge] = (src_bits, p_head); pad 33
    int node = (blockIdx.x * blockDim.x + threadIdx.x) >> 5;
    int lane = threadIdx.x & 31;
    int wslot = (threadIdx.x >> 5) & 7;
    if (node >= n) return;
    int s0 = g_rowptr[node], s1 = g_rowptr[node + 1];

    float4 adv = *(const float4*)&g_ad1[node * 4];
    int hl = lane & 15, half = lane >> 4;
    int head_g = hl >> 2;                  // head of the 8 dims this lane gathers
    float acc[8];
    #pragma unroll
    for (int i = 0; i < 8; i++) acc[i] = 0.f;
    float z0 = 0.f, z1 = 0.f, z2 = 0.f, z3 = 0.f;

    for (int base = s0; base < s1; base += 32) {
        int j = base + lane;
        int s = 0;
        float4 p = make_float4(0.f, 0.f, 0.f, 0.f);
        if (j < s1) {
            s = __ldg(&g_csr[j]);
            float4 asv = *(const float4*)&g_as1[s * 4];
            p.x = __expf(lrelu(asv.x + adv.x));
            p.y = __expf(lrelu(asv.y + adv.y));
            p.z = __expf(lrelu(asv.z + adv.z));
            p.w = __expf(lrelu(asv.w + adv.w));
            z0 += p.x; z1 += p.y; z2 += p.z; z3 += p.w;
        }
        __syncwarp();
        float fs = __int_as_float(s);
        sm_hp[wslot][0][lane] = make_float2(fs, p.x);
        sm_hp[wslot][1][lane] = make_float2(fs, p.y);
        sm_hp[wslot][2][lane] = make_float2(fs, p.z);
        sm_hp[wslot][3][lane] = make_float2(fs, p.w);
        __syncwarp();
        int cnt = min(32, s1 - base);
        int jb = half << 4;
        int je = min(cnt, jb + 16);
        #pragma unroll 4
        for (int jj = jb; jj < je; jj++) {
            float2 sp = sm_hp[wslot][head_g][jj];
            int   ss = __float_as_int(sp.x);
            float q  = sp.y;
            uint4 u = *(const uint4*)&h[ss * 128 + (hl << 3)];
            float2 f0 = __half22float2(*reinterpret_cast<__half2*>(&u.x));
            float2 f1 = __half22float2(*reinterpret_cast<__half2*>(&u.y));
            float2 f2 = __half22float2(*reinterpret_cast<__half2*>(&u.z));
            float2 f3 = __half22float2(*reinterpret_cast<__half2*>(&u.w));
            acc[0] += q * f0.x; acc[1] += q * f0.y;
            acc[2] += q * f1.x; acc[3] += q * f1.y;
            acc[4] += q * f2.x; acc[5] += q * f2.y;
            acc[6] += q * f3.x; acc[7] += q * f3.y;
        }
    }
    // merge the two halves
    #pragma unroll
    for (int i = 0; i < 8; i++) acc[i] += __shfl_xor_sync(FULL, acc[i], 16);
    #pragma unroll
    for (int off = 16; off; off >>= 1) {
        z0 += __shfl_xor_sync(FULL, z0, off);
        z1 += __shfl_xor_sync(FULL, z1, off);
        z2 += __shfl_xor_sync(FULL, z2, off);
        z3 += __shfl_xor_sync(FULL, z3, off);
    }
    if (half == 0) {
        float z = head_g == 0 ? z0 : head_g == 1 ? z1 : head_g == 2 ? z2 : z3;
        float inv = 1.f / z;
        int c = hl << 3;
        float4 b0 = *(const float4*)&b[c];
        float4 b1 = *(const float4*)&b[c + 4];
        __half2 v0 = __floats2half2_rn(elu(acc[0] * inv + b0.x), elu(acc[1] * inv + b0.y));
        __half2 v1 = __floats2half2_rn(elu(acc[2] * inv + b0.z), elu(acc[3] * inv + b0.w));
        __half2 v2 = __floats2half2_rn(elu(acc[4] * inv + b1.x), elu(acc[5] * inv + b1.y));
        __half2 v3 = __floats2half2_rn(elu(acc[6] * inv + b1.z), elu(acc[7] * inv + b1.w));
        uint4 st;
        st.x = *reinterpret_cast<unsigned*>(&v0);
        st.y = *reinterpret_cast<unsigned*>(&v1);
        st.z = *reinterpret_cast<unsigned*>(&v2);
        st.w = *reinterpret_cast<unsigned*>(&v3);
        *(uint4*)&out[node * 128 + c] = st;
    }
}

// ---------------- GAT aggregation, layer 2 (1 head) ----------------
__global__ void __launch_bounds__(256) att2_k(const __half* __restrict__ h,
                                              const float* __restrict__ b,
                                              float* __restrict__ out, int n) {
    __shared__ float2 sm2[8][33];
    int node = (blockIdx.x * blockDim.x + threadIdx.x) >> 5;
    int lane = threadIdx.x & 31;
    int wslot = (threadIdx.x >> 5) & 7;
    if (node >= n) return;
    int s0 = g_rowptr[node], s1 = g_rowptr[node + 1];

    float ad = g_ad2[node];
    int hl = lane & 15, half = lane >> 4;
    float acc[8];
    #pragma unroll
    for (int i = 0; i < 8; i++) acc[i] = 0.f;
    float z = 0.f;

    for (int base = s0; base < s1; base += 32) {
        int j = base + lane;
        int s = 0; float p = 0.f;
        if (j < s1) {
            s = __ldg(&g_csr[j]);
            p = __expf(lrelu(g_as2[s] + ad));
            z += p;
        }
        __syncwarp();
        sm2[wslot][lane] = make_float2(__int_as_float(s), p);
        __syncwarp();
        int cnt = min(32, s1 - base);
        int jb = half << 4;
        int je = min(cnt, jb + 16);
        #pragma unroll 4
        for (int jj = jb; jj < je; jj++) {
            float2 sp = sm2[wslot][jj];
            int   ss = __float_as_int(sp.x);
            float q  = sp.y;
            uint4 u = *(const uint4*)&h[ss * 128 + (hl << 3)];
            float2 f0 = __half22float2(*reinterpret_cast<__half2*>(&u.x));
            float2 f1 = __half22float2(*reinterpret_cast<__half2*>(&u.y));
            float2 f2 = __half22float2(*reinterpret_cast<__half2*>(&u.z));
            float2 f3 = __half22float2(*reinterpret_cast<__half2*>(&u.w));
            acc[0] += q * f0.x; acc[1] += q * f0.y;
            acc[2] += q * f1.x; acc[3] += q * f1.y;
            acc[4] += q * f2.x; acc[5] += q * f2.y;
            acc[6] += q * f3.x; acc[7] += q * f3.y;
        }
    }
    #pragma unroll
    for (int i = 0; i < 8; i++) acc[i] += __shfl_xor_sync(FULL, acc[i], 16);
    #pragma unroll
    for (int off = 16; off; off >>= 1)
        z += __shfl_xor_sync(FULL, z, off);
    if (half == 0) {
        float inv = 1.f / z;
        int c = hl << 3;
        float4 b0 = *(const float4*)&b[c];
        float4 b1 = *(const float4*)&b[c + 4];
        float4 o0, o1;
        o0.x = elu(acc[0] * inv + b0.x);
        o0.y = elu(acc[1] * inv + b0.y);
        o0.z = elu(acc[2] * inv + b0.z);
        o0.w = elu(acc[3] * inv + b0.w);
        o1.x = elu(acc[4] * inv + b1.x);
        o1.y = elu(acc[5] * inv + b1.y);
        o1.z = elu(acc[6] * inv + b1.z);
        o1.w = elu(acc[7] * inv + b1.w);
        *(float4*)&out[node * 128 + c]     = o0;
        *(float4*)&out[node * 128 + c + 4] = o1;
    }
}

// ---------------- final linear head: [n,128] @ [128,40] + b ----------------
__global__ void head_k(const float* __restrict__ A, const float* __restrict__ W,
                       const float* __restrict__ b, float* __restrict__ out, int n) {
    int i = blockIdx.x * blockDim.x + threadIdx.x;
    if (i >= n * 40) return;
    int row = i / 40, c = i - row * 40;
    const float* xr = &A[row * 128];
    float acc = b[c];
    #pragma unroll 8
    for (int k = 0; k < 128; k++)
        acc += xr[k] * __ldg(&W[k * 40 + c]);
    out[i] = acc;
}

// ---------------- launch ----------------
extern "C" void kernel_launch(void* const* d_in, const int* in_sizes, int n_in,
                              void* d_out, int out_size) {
    const float* x   = (const float*)d_in[0];
    const int*   ei  = (const int*)  d_in[1];
    const float* W1  = (const float*)d_in[2];
    const float* as1 = (const float*)d_in[3];
    const float* ad1 = (const float*)d_in[4];
    const float* b1  = (const float*)d_in[5];
    const float* W2  = (const float*)d_in[6];
    const float* as2 = (const float*)d_in[7];
    const float* ad2 = (const float*)d_in[8];
    const float* b2  = (const float*)d_in[9];
    const float* Wl  = (const float*)d_in[10];
    const float* bl  = (const float*)d_in[11];
    float* out = (float*)d_out;

    const int n = in_sizes[0] / 128;   // 10000
    const int e = in_sizes[1] / 2;     // 640000

    __half *B1t, *B2t, *h1h, *h2h, *o1h;
    float *o2, *pas1, *pad1, *pas2, *pad2;
    cudaGetSymbolAddress((void**)&B1t, g_B1t);
    cudaGetSymbolAddress((void**)&B2t, g_B2t);
    cudaGetSymbolAddress((void**)&h1h, g_h1h);
    cudaGetSymbolAddress((void**)&h2h, g_h2h);
    cudaGetSymbolAddress((void**)&o1h, g_o1h);
    cudaGetSymbolAddress((void**)&o2,  g_o2);
    cudaGetSymbolAddress((void**)&pas1, g_as1);
    cudaGetSymbolAddress((void**)&pad1, g_ad1);
    cudaGetSymbolAddress((void**)&pas2, g_as2);
    cudaGetSymbolAddress((void**)&pad2, g_ad2);

    int q = e >> 2, tail = e & 3;

    // K1: hist + weight convert (independent; co-scheduled)
    int HB = (q + tail + 255) / 256;
    int WB = (2 * 128 * 128 / 4 + 255) / 256;
    combo1_k<<<HB + WB, 256>>>(ei, e, W1, W2, B1t, B2t, HB);

    // K2: scan (rowptr + self-loop slots + deg reset)
    scan_k<<<1, 1024>>>(n);

    // K3: fill + layer-1 GEMM (independent; co-scheduled)
    int FB = (q + tail + 127) / 128;
    int GB = (n + 15) / 16;
    combo2_k<<<FB + GB, 128>>>(ei, e, x, B1t, as1, ad1, h1h, pas1, pad1, n, FB);

    // K4: layer-1 aggregation
    att1_k<<<(n * 32 + 255) / 256, 256>>>(h1h, b1, o1h, n);

    // K5: layer-2 GEMM
    gemm2_k<<<(n + 15) / 16, 128>>>(o1h, B2t, as2, ad2, h2h, pas2, pad2, n);

    // K6: layer-2 aggregation
    att2_k<<<(n * 32 + 255) / 256, 256>>>(h2h, b2, o2, n);

    // K7: head
    head_k<<<(n * 40 + 255) / 256, 256>>>(o2, Wl, bl, out, n);
}